// round 2
// baseline (speedup 1.0000x reference)
#include <cuda_runtime.h>
#include <math.h>

// Problem constants
#define BB 16
#define LQ 2048
#define LC 2048
#define DD 1024

// GEMM tile config
#define BM 128
#define BN 128
#define BK 8

// Scratch: ctx_proj [B, Lc, D] and context [B, Lq, D]
__device__ float g_ctx[(long long)BB * LC * DD];
__device__ float g_tmp[(long long)BB * LQ * DD];

// C[m,n] = alpha * sum_k A[m,k] * B'[k,n] (+ beta*C)
// TB=true : B is [N,K] row-major (B'[k,n] = B[n*K+k])   -> NT gemm
// TB=false: B is [K,N] row-major                        -> NN gemm
// All of M, N multiples of 128; K multiple of 8 (guaranteed by problem shapes).
template <bool TB>
__global__ __launch_bounds__(256)
void sgemm_kernel(const float* __restrict__ A, const float* __restrict__ Bm,
                  float* __restrict__ C,
                  int M, int N, int K,
                  long long sA, long long sB, long long sC,
                  float alpha, float beta)
{
    __shared__ float As[BK][BM];
    __shared__ float Bs[BK][BN];

    const int bz = blockIdx.z;
    const float* Ab = A  + (long long)bz * sA;
    const float* Bb = Bm + (long long)bz * sB;
    float*       Cb = C  + (long long)bz * sC;

    const int bm = blockIdx.y, bn = blockIdx.x;
    const int tid = threadIdx.x;

    // per-thread output sub-tiles: rows {ra..ra+3, ra+64..ra+67}, cols {ca..ca+3, ca+64..ca+67}
    const int ra = (tid >> 4) * 4;   // 0..60
    const int ca = (tid & 15) * 4;   // 0..60

    float acc[8][8];
#pragma unroll
    for (int i = 0; i < 8; i++)
#pragma unroll
        for (int j = 0; j < 8; j++) acc[i][j] = 0.0f;

    // A tile loader: 128 rows x 8 cols, k-contiguous in gmem -> transpose into As[k][m]
    const int arow = tid >> 1;          // 0..127
    const int aq   = (tid & 1) * 4;     // 0 or 4
    const float* Aptr = Ab + (long long)(bm * BM + arow) * K + aq;

    // B tile loader
    const float* Bptr;
    int brow = 0, bq = 0, krow = 0, nq = 0;
    if (TB) {
        brow = tid >> 1;                // 0..127 (N rows)
        bq   = (tid & 1) * 4;
        Bptr = Bb + (long long)(bn * BN + brow) * K + bq;
    } else {
        krow = tid >> 5;                // 0..7
        nq   = (tid & 31) * 4;          // 0..124
        Bptr = Bb + (long long)krow * N + bn * BN + nq;
    }

    for (int kt = 0; kt < K; kt += BK) {
        float4 av = *(const float4*)(Aptr + kt);
        As[aq + 0][arow] = av.x;
        As[aq + 1][arow] = av.y;
        As[aq + 2][arow] = av.z;
        As[aq + 3][arow] = av.w;

        if (TB) {
            float4 bv = *(const float4*)(Bptr + kt);
            Bs[bq + 0][brow] = bv.x;
            Bs[bq + 1][brow] = bv.y;
            Bs[bq + 2][brow] = bv.z;
            Bs[bq + 3][brow] = bv.w;
        } else {
            float4 bv = *(const float4*)(Bptr + (long long)kt * N);
            *(float4*)&Bs[krow][nq] = bv;
        }
        __syncthreads();

#pragma unroll
        for (int kk = 0; kk < BK; kk++) {
            float4 a0 = *(const float4*)&As[kk][ra];
            float4 a1 = *(const float4*)&As[kk][ra + 64];
            float4 b0 = *(const float4*)&Bs[kk][ca];
            float4 b1 = *(const float4*)&Bs[kk][ca + 64];
            float ar[8] = {a0.x, a0.y, a0.z, a0.w, a1.x, a1.y, a1.z, a1.w};
            float br[8] = {b0.x, b0.y, b0.z, b0.w, b1.x, b1.y, b1.z, b1.w};
#pragma unroll
            for (int i = 0; i < 8; i++)
#pragma unroll
                for (int j = 0; j < 8; j++)
                    acc[i][j] += ar[i] * br[j];
        }
        __syncthreads();
    }

    // Epilogue
#pragma unroll
    for (int i = 0; i < 8; i++) {
        const int row = bm * BM + ((i < 4) ? (ra + i) : (ra + 60 + i));
        float* crow = Cb + (long long)row * N + bn * BN;
#pragma unroll
        for (int g = 0; g < 2; g++) {
            const int col = ca + g * 64;
            float4 o;
            o.x = alpha * acc[i][g * 4 + 0];
            o.y = alpha * acc[i][g * 4 + 1];
            o.z = alpha * acc[i][g * 4 + 2];
            o.w = alpha * acc[i][g * 4 + 3];
            if (beta != 0.0f) {
                float4 c = *(float4*)(crow + col);
                o.x += beta * c.x; o.y += beta * c.y;
                o.z += beta * c.z; o.w += beta * c.w;
            }
            *(float4*)(crow + col) = o;
        }
    }
}

// Row softmax, in place. One block per row; ncols == 2048, 256 threads -> 8 elems/thread.
__global__ __launch_bounds__(256)
void softmax_kernel(float* __restrict__ data)
{
    const long long row = blockIdx.x;
    float* p = data + row * (long long)LC;
    const int tid = threadIdx.x;
    const int lane = tid & 31, wid = tid >> 5;

    __shared__ float sred[8];
    __shared__ float sbcast;

    float4 x0 = ((const float4*)p)[tid];
    float4 x1 = ((const float4*)p)[tid + 256];

    float m = fmaxf(fmaxf(fmaxf(x0.x, x0.y), fmaxf(x0.z, x0.w)),
                    fmaxf(fmaxf(x1.x, x1.y), fmaxf(x1.z, x1.w)));
#pragma unroll
    for (int off = 16; off; off >>= 1) m = fmaxf(m, __shfl_xor_sync(0xffffffffu, m, off));
    if (lane == 0) sred[wid] = m;
    __syncthreads();
    if (tid == 0) {
        float t = sred[0];
#pragma unroll
        for (int w = 1; w < 8; w++) t = fmaxf(t, sred[w]);
        sbcast = t;
    }
    __syncthreads();
    const float rowmax = sbcast;
    __syncthreads();

    float e[8];
    e[0] = expf(x0.x - rowmax); e[1] = expf(x0.y - rowmax);
    e[2] = expf(x0.z - rowmax); e[3] = expf(x0.w - rowmax);
    e[4] = expf(x1.x - rowmax); e[5] = expf(x1.y - rowmax);
    e[6] = expf(x1.z - rowmax); e[7] = expf(x1.w - rowmax);

    float s = 0.0f;
#pragma unroll
    for (int i = 0; i < 8; i++) s += e[i];
#pragma unroll
    for (int off = 16; off; off >>= 1) s += __shfl_xor_sync(0xffffffffu, s, off);
    if (lane == 0) sred[wid] = s;
    __syncthreads();
    if (tid == 0) {
        float t = 0.0f;
#pragma unroll
        for (int w = 0; w < 8; w++) t += sred[w];
        sbcast = t;
    }
    __syncthreads();
    const float inv = 1.0f / sbcast;

    float4 o0 = make_float4(e[0] * inv, e[1] * inv, e[2] * inv, e[3] * inv);
    float4 o1 = make_float4(e[4] * inv, e[5] * inv, e[6] * inv, e[7] * inv);
    ((float4*)p)[tid]       = o0;
    ((float4*)p)[tid + 256] = o1;
}

extern "C" void kernel_launch(void* const* d_in, const int* in_sizes, int n_in,
                              void* d_out, int out_size)
{
    const float* query = (const float*)d_in[0];  // [B, Lq, D]
    const float* bank  = (const float*)d_in[1];  // [B, Lc, D]
    const float* Wc    = (const float*)d_in[2];  // [D, D]
    const float* Woq   = (const float*)d_in[3];  // [D, D]
    const float* Woc   = (const float*)d_in[4];  // [D, D]

    float* out  = (float*)d_out;                               // [B, Lq, D]
    float* attn = out + (long long)BB * LQ * DD;               // [B, Lq, Lc]

    float* ctx; cudaGetSymbolAddress((void**)&ctx, g_ctx);
    float* tmp; cudaGetSymbolAddress((void**)&tmp, g_tmp);

    const dim3 blk(256);
    const float inv_sqrt_d = 0.03125f;  // 1/sqrt(1024)

    // 1. ctx_proj[b,k,e] = sum_d bank[b,k,d] * Wc[e,d]  (flattened M = B*Lc)
    sgemm_kernel<true><<<dim3(DD / BN, (BB * LC) / BM, 1), blk>>>(
        bank, Wc, ctx, BB * LC, DD, DD, 0, 0, 0, 1.0f, 0.0f);

    // 2. score[b,q,k] = (1/32) * sum_d query[b,q,d] * ctx[b,k,d]  -> attn region
    sgemm_kernel<true><<<dim3(LC / BN, LQ / BM, BB), blk>>>(
        query, ctx, attn, LQ, LC, DD,
        (long long)LQ * DD, (long long)LC * DD, (long long)LQ * LC,
        inv_sqrt_d, 0.0f);

    // 3. softmax rows, in place
    softmax_kernel<<<BB * LQ, blk>>>(attn);

    // 4. context[b,q,d] = sum_k attn[b,q,k] * bank[b,k,d]  (NN)
    sgemm_kernel<false><<<dim3(DD / BN, LQ / BM, BB), blk>>>(
        attn, bank, tmp, LQ, DD, LC,
        (long long)LQ * LC, (long long)LC * DD, (long long)LQ * DD,
        1.0f, 0.0f);

    // 5. out = context @ Woc^T
    sgemm_kernel<true><<<dim3(DD / BN, (BB * LQ) / BM, 1), blk>>>(
        tmp, Woc, out, BB * LQ, DD, DD, 0, 0, 0, 1.0f, 0.0f);

    // 6. out += query @ Woq^T
    sgemm_kernel<true><<<dim3(DD / BN, (BB * LQ) / BM, 1), blk>>>(
        query, Woq, out, BB * LQ, DD, DD, 0, 0, 0, 1.0f, 1.0f);
}

// round 3
// speedup vs baseline: 1.0007x; 1.0007x over previous
#include <cuda_runtime.h>
#include <math.h>

// Problem constants
#define BB 16
#define LQ 2048
#define LC 2048
#define DD 1024

// GEMM tile config
#define BM 128
#define BN 128
#define BK 8

// Scratch: ctx_proj [B, Lc, D] and context [B, Lq, D]
__device__ float g_ctx[(long long)BB * LC * DD];
__device__ float g_tmp[(long long)BB * LQ * DD];

// C[m,n] = alpha * sum_k A[m,k] * B'[k,n] (+ beta*C)
// TB=true : B is [N,K] row-major (B'[k,n] = B[n*K+k])   -> NT gemm
// TB=false: B is [K,N] row-major                        -> NN gemm
// All of M, N multiples of 128; K multiple of 8 (guaranteed by problem shapes).
template <bool TB>
__global__ __launch_bounds__(256)
void sgemm_kernel(const float* __restrict__ A, const float* __restrict__ Bm,
                  float* __restrict__ C,
                  int M, int N, int K,
                  long long sA, long long sB, long long sC,
                  float alpha, float beta)
{
    __shared__ float As[BK][BM];
    __shared__ float Bs[BK][BN];

    const int bz = blockIdx.z;
    const float* Ab = A  + (long long)bz * sA;
    const float* Bb = Bm + (long long)bz * sB;
    float*       Cb = C  + (long long)bz * sC;

    const int bm = blockIdx.y, bn = blockIdx.x;
    const int tid = threadIdx.x;

    // per-thread output sub-tiles: rows {ra..ra+3, ra+64..ra+67}, cols {ca..ca+3, ca+64..ca+67}
    const int ra = (tid >> 4) * 4;   // 0..60
    const int ca = (tid & 15) * 4;   // 0..60

    float acc[8][8];
#pragma unroll
    for (int i = 0; i < 8; i++)
#pragma unroll
        for (int j = 0; j < 8; j++) acc[i][j] = 0.0f;

    // A tile loader: 128 rows x 8 cols, k-contiguous in gmem -> transpose into As[k][m]
    const int arow = tid >> 1;          // 0..127
    const int aq   = (tid & 1) * 4;     // 0 or 4
    const float* Aptr = Ab + (long long)(bm * BM + arow) * K + aq;

    // B tile loader
    const float* Bptr;
    int brow = 0, bq = 0, krow = 0, nq = 0;
    if (TB) {
        brow = tid >> 1;                // 0..127 (N rows)
        bq   = (tid & 1) * 4;
        Bptr = Bb + (long long)(bn * BN + brow) * K + bq;
    } else {
        krow = tid >> 5;                // 0..7
        nq   = (tid & 31) * 4;          // 0..124
        Bptr = Bb + (long long)krow * N + bn * BN + nq;
    }

    for (int kt = 0; kt < K; kt += BK) {
        float4 av = *(const float4*)(Aptr + kt);
        As[aq + 0][arow] = av.x;
        As[aq + 1][arow] = av.y;
        As[aq + 2][arow] = av.z;
        As[aq + 3][arow] = av.w;

        if (TB) {
            float4 bv = *(const float4*)(Bptr + kt);
            Bs[bq + 0][brow] = bv.x;
            Bs[bq + 1][brow] = bv.y;
            Bs[bq + 2][brow] = bv.z;
            Bs[bq + 3][brow] = bv.w;
        } else {
            float4 bv = *(const float4*)(Bptr + (long long)kt * N);
            *(float4*)&Bs[krow][nq] = bv;
        }
        __syncthreads();

#pragma unroll
        for (int kk = 0; kk < BK; kk++) {
            float4 a0 = *(const float4*)&As[kk][ra];
            float4 a1 = *(const float4*)&As[kk][ra + 64];
            float4 b0 = *(const float4*)&Bs[kk][ca];
            float4 b1 = *(const float4*)&Bs[kk][ca + 64];
            float ar[8] = {a0.x, a0.y, a0.z, a0.w, a1.x, a1.y, a1.z, a1.w};
            float br[8] = {b0.x, b0.y, b0.z, b0.w, b1.x, b1.y, b1.z, b1.w};
#pragma unroll
            for (int i = 0; i < 8; i++)
#pragma unroll
                for (int j = 0; j < 8; j++)
                    acc[i][j] += ar[i] * br[j];
        }
        __syncthreads();
    }

    // Epilogue
#pragma unroll
    for (int i = 0; i < 8; i++) {
        const int row = bm * BM + ((i < 4) ? (ra + i) : (ra + 60 + i));
        float* crow = Cb + (long long)row * N + bn * BN;
#pragma unroll
        for (int g = 0; g < 2; g++) {
            const int col = ca + g * 64;
            float4 o;
            o.x = alpha * acc[i][g * 4 + 0];
            o.y = alpha * acc[i][g * 4 + 1];
            o.z = alpha * acc[i][g * 4 + 2];
            o.w = alpha * acc[i][g * 4 + 3];
            if (beta != 0.0f) {
                float4 c = *(float4*)(crow + col);
                o.x += beta * c.x; o.y += beta * c.y;
                o.z += beta * c.z; o.w += beta * c.w;
            }
            *(float4*)(crow + col) = o;
        }
    }
}

// Row softmax, in place. One block per row; ncols == 2048, 256 threads -> 8 elems/thread.
__global__ __launch_bounds__(256)
void softmax_kernel(float* __restrict__ data)
{
    const long long row = blockIdx.x;
    float* p = data + row * (long long)LC;
    const int tid = threadIdx.x;
    const int lane = tid & 31, wid = tid >> 5;

    __shared__ float sred[8];
    __shared__ float sbcast;

    float4 x0 = ((const float4*)p)[tid];
    float4 x1 = ((const float4*)p)[tid + 256];

    float m = fmaxf(fmaxf(fmaxf(x0.x, x0.y), fmaxf(x0.z, x0.w)),
                    fmaxf(fmaxf(x1.x, x1.y), fmaxf(x1.z, x1.w)));
#pragma unroll
    for (int off = 16; off; off >>= 1) m = fmaxf(m, __shfl_xor_sync(0xffffffffu, m, off));
    if (lane == 0) sred[wid] = m;
    __syncthreads();
    if (tid == 0) {
        float t = sred[0];
#pragma unroll
        for (int w = 1; w < 8; w++) t = fmaxf(t, sred[w]);
        sbcast = t;
    }
    __syncthreads();
    const float rowmax = sbcast;
    __syncthreads();

    float e[8];
    e[0] = expf(x0.x - rowmax); e[1] = expf(x0.y - rowmax);
    e[2] = expf(x0.z - rowmax); e[3] = expf(x0.w - rowmax);
    e[4] = expf(x1.x - rowmax); e[5] = expf(x1.y - rowmax);
    e[6] = expf(x1.z - rowmax); e[7] = expf(x1.w - rowmax);

    float s = 0.0f;
#pragma unroll
    for (int i = 0; i < 8; i++) s += e[i];
#pragma unroll
    for (int off = 16; off; off >>= 1) s += __shfl_xor_sync(0xffffffffu, s, off);
    if (lane == 0) sred[wid] = s;
    __syncthreads();
    if (tid == 0) {
        float t = 0.0f;
#pragma unroll
        for (int w = 0; w < 8; w++) t += sred[w];
        sbcast = t;
    }
    __syncthreads();
    const float inv = 1.0f / sbcast;

    float4 o0 = make_float4(e[0] * inv, e[1] * inv, e[2] * inv, e[3] * inv);
    float4 o1 = make_float4(e[4] * inv, e[5] * inv, e[6] * inv, e[7] * inv);
    ((float4*)p)[tid]       = o0;
    ((float4*)p)[tid + 256] = o1;
}

extern "C" void kernel_launch(void* const* d_in, const int* in_sizes, int n_in,
                              void* d_out, int out_size)
{
    const float* query = (const float*)d_in[0];  // [B, Lq, D]
    const float* bank  = (const float*)d_in[1];  // [B, Lc, D]
    const float* Wc    = (const float*)d_in[2];  // [D, D]
    const float* Woq   = (const float*)d_in[3];  // [D, D]
    const float* Woc   = (const float*)d_in[4];  // [D, D]

    float* out  = (float*)d_out;                               // [B, Lq, D]
    float* attn = out + (long long)BB * LQ * DD;               // [B, Lq, Lc]

    float* ctx; cudaGetSymbolAddress((void**)&ctx, g_ctx);
    float* tmp; cudaGetSymbolAddress((void**)&tmp, g_tmp);

    const dim3 blk(256);
    const float inv_sqrt_d = 0.03125f;  // 1/sqrt(1024)

    // 1. ctx_proj[b,k,e] = sum_d bank[b,k,d] * Wc[e,d]  (flattened M = B*Lc)
    sgemm_kernel<true><<<dim3(DD / BN, (BB * LC) / BM, 1), blk>>>(
        bank, Wc, ctx, BB * LC, DD, DD, 0, 0, 0, 1.0f, 0.0f);

    // 2. score[b,q,k] = (1/32) * sum_d query[b,q,d] * ctx[b,k,d]  -> attn region
    sgemm_kernel<true><<<dim3(LC / BN, LQ / BM, BB), blk>>>(
        query, ctx, attn, LQ, LC, DD,
        (long long)LQ * DD, (long long)LC * DD, (long long)LQ * LC,
        inv_sqrt_d, 0.0f);

    // 3. softmax rows, in place
    softmax_kernel<<<BB * LQ, blk>>>(attn);

    // 4. context[b,q,d] = sum_k attn[b,q,k] * bank[b,k,d]  (NN)
    sgemm_kernel<false><<<dim3(DD / BN, LQ / BM, BB), blk>>>(
        attn, bank, tmp, LQ, DD, LC,
        (long long)LQ * LC, (long long)LC * DD, (long long)LQ * DD,
        1.0f, 0.0f);

    // 5. out = context @ Woc^T
    sgemm_kernel<true><<<dim3(DD / BN, (BB * LQ) / BM, 1), blk>>>(
        tmp, Woc, out, BB * LQ, DD, DD, 0, 0, 0, 1.0f, 0.0f);

    // 6. out += query @ Woq^T
    sgemm_kernel<true><<<dim3(DD / BN, (BB * LQ) / BM, 1), blk>>>(
        query, Woq, out, BB * LQ, DD, DD, 0, 0, 0, 1.0f, 1.0f);
}

// round 5
// speedup vs baseline: 3.2157x; 3.2135x over previous
#include <cuda_runtime.h>
#include <cuda_fp16.h>
#include <math.h>
#include <stdint.h>

#define BB 16
#define LQ 2048
#define LC 2048
#define DD 1024
#define NQ_ELEMS  (BB * LQ * DD)
#define NB_ELEMS  (BB * LC * DD)
#define NW_ELEMS  (DD * DD)
#define NA_ELEMS  ((long long)BB * LQ * LC)

// scratch
__device__ __half g_qh[NQ_ELEMS], g_ql[NQ_ELEMS];
__device__ __half g_bh[NB_ELEMS], g_bl[NB_ELEMS];
__device__ __half g_bTh[NB_ELEMS];
__device__ __half g_ch[NB_ELEMS], g_cl[NB_ELEMS];
__device__ __half g_ah[NA_ELEMS];
__device__ __half g_vh[NQ_ELEMS];
__device__ __half g_wch[NW_ELEMS], g_wcl[NW_ELEMS];
__device__ __half g_woqh[NW_ELEMS], g_woql[NW_ELEMS];
__device__ __half g_woch[NW_ELEMS], g_wocl[NW_ELEMS];

// ---- helpers ----
__device__ __forceinline__ uint32_t smem_u32(const void* p) {
    uint32_t a;
    asm("{ .reg .u64 t; cvta.to.shared.u64 t, %1; cvt.u32.u64 %0, t; }" : "=r"(a) : "l"(p));
    return a;
}
__device__ __forceinline__ void cp16(uint32_t dst, const void* src) {
    asm volatile("cp.async.cg.shared.global [%0], [%1], 16;" :: "r"(dst), "l"(src) : "memory");
}
__device__ __forceinline__ void cp_commit() { asm volatile("cp.async.commit_group;" ::: "memory"); }
template <int N> __device__ __forceinline__ void cp_wait() {
    asm volatile("cp.async.wait_group %0;" :: "n"(N) : "memory");
}
__device__ __forceinline__ void ldm4(uint32_t* r, uint32_t addr) {
    asm volatile("ldmatrix.sync.aligned.m8n8.x4.shared.b16 {%0,%1,%2,%3}, [%4];"
                 : "=r"(r[0]), "=r"(r[1]), "=r"(r[2]), "=r"(r[3]) : "r"(addr));
}
__device__ __forceinline__ void mma16816(float* c, const uint32_t* a, const uint32_t* b) {
    asm volatile("mma.sync.aligned.m16n8k16.row.col.f32.f16.f16.f32 "
                 "{%0,%1,%2,%3},{%4,%5,%6,%7},{%8,%9},{%0,%1,%2,%3};"
                 : "+f"(c[0]), "+f"(c[1]), "+f"(c[2]), "+f"(c[3])
                 : "r"(a[0]), "r"(a[1]), "r"(a[2]), "r"(a[3]), "r"(b[0]), "r"(b[1]));
}

// ---- HMMA GEMM: C[M,N] = alpha * sum_seg A_s @ B_s^T ----
// A_s: [M,K] row-major fp16 (ld = K); B_s: [N,K] row-major fp16 (ld = K).
#define BM 128
#define BN 128
#define BK 32
#define STRD 40   // BK + 8 pad (halfwords)

struct GemmArgs {
    const __half *a0, *b0, *a1, *b1, *a2, *b2;
};

template <int MODE>  // 0: fp32 out; 1: split fp16 out (Ch,Cl); 2: single fp16 out (Ch)
__global__ void __launch_bounds__(256, 2)
hgemm(GemmArgs seg, int nseg, int K,
      float* __restrict__ Cf, __half* __restrict__ Ch, __half* __restrict__ Cl,
      int ldc, long long sA, long long sB, long long sC, float alpha)
{
    __shared__ __half sAb[2][BM * STRD];
    __shared__ __half sBb[2][BN * STRD];

    const int tid = threadIdx.x, lane = tid & 31, wid = tid >> 5;
    const int warp_m = wid & 3, warp_n = wid >> 2;   // 4 x 2 warp grid -> 32x64 per warp
    const int bm = blockIdx.y, bn = blockIdx.x, bz = blockIdx.z;

    const __half* Aseg[3] = { seg.a0, seg.a1, seg.a2 };
    const __half* Bseg[3] = { seg.b0, seg.b1, seg.b2 };

    const int tps = K / BK;          // tiles per segment
    const int CT = nseg * tps;

    // loader: 512 16B-chunks per operand; thread handles chunks {tid, tid+256}
    const int lrow0 = tid >> 2, loff0 = (tid & 3) * 8;
    const int lrow1 = (tid + 256) >> 2, loff1 = ((tid + 256) & 3) * 8;

    const uint32_t saA[2] = { smem_u32(&sAb[0][0]), smem_u32(&sAb[1][0]) };
    const uint32_t saB[2] = { smem_u32(&sBb[0][0]), smem_u32(&sBb[1][0]) };

    float acc[2][8][4];
#pragma unroll
    for (int i = 0; i < 2; i++)
#pragma unroll
        for (int j = 0; j < 8; j++)
#pragma unroll
            for (int q = 0; q < 4; q++) acc[i][j][q] = 0.0f;

    auto load_tile = [&](int t, int buf) {
        const int s = t / tps, kk = (t - s * tps) * BK;
        const __half* Ab = Aseg[s] + bz * sA + (long long)(bm * BM) * K + kk;
        const __half* Bb = Bseg[s] + bz * sB + (long long)(bn * BN) * K + kk;
        cp16(saA[buf] + (uint32_t)(lrow0 * STRD + loff0) * 2, Ab + (long long)lrow0 * K + loff0);
        cp16(saA[buf] + (uint32_t)(lrow1 * STRD + loff1) * 2, Ab + (long long)lrow1 * K + loff1);
        cp16(saB[buf] + (uint32_t)(lrow0 * STRD + loff0) * 2, Bb + (long long)lrow0 * K + loff0);
        cp16(saB[buf] + (uint32_t)(lrow1 * STRD + loff1) * 2, Bb + (long long)lrow1 * K + loff1);
        cp_commit();
    };

    // ldmatrix per-thread byte offsets
    const uint32_t a_off = (uint32_t)(((warp_m * 32 + (lane & 15)) * STRD + (lane >> 4) * 8) * 2);
    uint32_t b_off[4];
#pragma unroll
    for (int nf = 0; nf < 4; nf++)
        b_off[nf] = (uint32_t)(((warp_n * 64 + nf * 16 + ((lane >> 4) << 3) + (lane & 7)) * STRD
                                + ((lane >> 3) & 1) * 8) * 2);

    load_tile(0, 0);

    for (int t = 0; t < CT; ++t) {
        if (t + 1 < CT) { load_tile(t + 1, (t + 1) & 1); cp_wait<1>(); }
        else            { cp_wait<0>(); }
        __syncthreads();

        const uint32_t baA = saA[t & 1], baB = saB[t & 1];
#pragma unroll
        for (int kk = 0; kk < 2; kk++) {
            const uint32_t kadd = kk * 32;   // 16 halfwords = 32 bytes
            uint32_t a[2][4], b[8][2];
            ldm4(a[0], baA + a_off + kadd);
            ldm4(a[1], baA + a_off + kadd + 16 * STRD * 2);
#pragma unroll
            for (int nf = 0; nf < 4; nf++) {
                uint32_t r[4];
                ldm4(r, baB + b_off[nf] + kadd);
                b[2 * nf][0] = r[0]; b[2 * nf][1] = r[1];
                b[2 * nf + 1][0] = r[2]; b[2 * nf + 1][1] = r[3];
            }
#pragma unroll
            for (int im = 0; im < 2; im++)
#pragma unroll
                for (int in = 0; in < 8; in++)
                    mma16816(acc[im][in], a[im], b[in]);
        }
        __syncthreads();
    }

    // epilogue
    const int gr = lane >> 2, qd = lane & 3;
#pragma unroll
    for (int im = 0; im < 2; im++) {
#pragma unroll
        for (int in = 0; in < 8; in++) {
            const long long row0 = (long long)bm * BM + warp_m * 32 + im * 16 + gr;
            const int col = bn * BN + warp_n * 64 + in * 8 + qd * 2;
#pragma unroll
            for (int h = 0; h < 2; h++) {
                const long long row = row0 + h * 8;
                const float v0 = alpha * acc[im][in][2 * h + 0];
                const float v1 = alpha * acc[im][in][2 * h + 1];
                if (MODE == 0) {
                    float2* dst = (float2*)(Cf + bz * sC + row * ldc + col);
                    *dst = make_float2(v0, v1);
                } else if (MODE == 1) {
                    const __half h0 = __float2half_rn(v0), h1 = __float2half_rn(v1);
                    const __half l0 = __float2half_rn(v0 - __half2float(h0));
                    const __half l1 = __float2half_rn(v1 - __half2float(h1));
                    *(__half2*)(Ch + bz * sC + row * ldc + col) = __halves2half2(h0, h1);
                    *(__half2*)(Cl + bz * sC + row * ldc + col) = __halves2half2(l0, l1);
                } else {
                    *(__half2*)(Ch + bz * sC + row * ldc + col) =
                        __halves2half2(__float2half_rn(v0), __float2half_rn(v1));
                }
            }
        }
    }
}

// ---- fp32 -> fp16 hi/lo split ----
__global__ void __launch_bounds__(256)
split_f16(const float4* __restrict__ src, __half2* __restrict__ hi, __half2* __restrict__ lo, int n4)
{
    for (int i = blockIdx.x * blockDim.x + threadIdx.x; i < n4; i += gridDim.x * blockDim.x) {
        const float4 v = src[i];
        const __half hx = __float2half_rn(v.x), hy = __float2half_rn(v.y);
        const __half hz = __float2half_rn(v.z), hw = __float2half_rn(v.w);
        hi[2 * i]     = __halves2half2(hx, hy);
        hi[2 * i + 1] = __halves2half2(hz, hw);
        lo[2 * i]     = __halves2half2(__float2half_rn(v.x - __half2float(hx)),
                                       __float2half_rn(v.y - __half2float(hy)));
        lo[2 * i + 1] = __halves2half2(__float2half_rn(v.z - __half2float(hz)),
                                       __float2half_rn(v.w - __half2float(hw)));
    }
}

// ---- bank [b,K,D] fp32 -> bankT [b,D,K] fp16 single ----
__global__ void __launch_bounds__(256)
transpose_h(const float* __restrict__ src, __half* __restrict__ dst)
{
    __shared__ float t[32][33];
    const int tx = threadIdx.x, ty = threadIdx.y;       // (32, 8)
    const int kb = blockIdx.y, db = blockIdx.x, b = blockIdx.z;
    const float* s = src + (long long)b * LC * DD;
#pragma unroll
    for (int r = 0; r < 4; r++)
        t[ty + r * 8][tx] = s[(long long)(kb * 32 + ty + r * 8) * DD + db * 32 + tx];
    __syncthreads();
    __half* o = dst + (long long)b * DD * LC;
#pragma unroll
    for (int r = 0; r < 4; r++) {
        const int drow = db * 32 + ty + r * 8;
        const int kcol = kb * 32 + tx;
        o[(long long)drow * LC + kcol] = __float2half_rn(t[tx][ty + r * 8]);
    }
}

// ---- softmax (fp32 in/out in place) + fp16 single emit ----
__global__ void __launch_bounds__(256)
softmax_emit(float* __restrict__ data, __half* __restrict__ ah)
{
    const long long row = blockIdx.x;
    float* p = data + row * (long long)LC;
    const int tid = threadIdx.x;
    const int lane = tid & 31, wid = tid >> 5;
    __shared__ float sred[8];
    __shared__ float sbcast;

    float4 x0 = ((const float4*)p)[tid];
    float4 x1 = ((const float4*)p)[tid + 256];

    float m = fmaxf(fmaxf(fmaxf(x0.x, x0.y), fmaxf(x0.z, x0.w)),
                    fmaxf(fmaxf(x1.x, x1.y), fmaxf(x1.z, x1.w)));
#pragma unroll
    for (int off = 16; off; off >>= 1) m = fmaxf(m, __shfl_xor_sync(0xffffffffu, m, off));
    if (lane == 0) sred[wid] = m;
    __syncthreads();
    if (tid == 0) {
        float t = sred[0];
#pragma unroll
        for (int w = 1; w < 8; w++) t = fmaxf(t, sred[w]);
        sbcast = t;
    }
    __syncthreads();
    const float rowmax = sbcast;
    __syncthreads();

    float e[8];
    e[0] = expf(x0.x - rowmax); e[1] = expf(x0.y - rowmax);
    e[2] = expf(x0.z - rowmax); e[3] = expf(x0.w - rowmax);
    e[4] = expf(x1.x - rowmax); e[5] = expf(x1.y - rowmax);
    e[6] = expf(x1.z - rowmax); e[7] = expf(x1.w - rowmax);

    float ssum = 0.0f;
#pragma unroll
    for (int i = 0; i < 8; i++) ssum += e[i];
#pragma unroll
    for (int off = 16; off; off >>= 1) ssum += __shfl_xor_sync(0xffffffffu, ssum, off);
    if (lane == 0) sred[wid] = ssum;
    __syncthreads();
    if (tid == 0) {
        float t = 0.0f;
#pragma unroll
        for (int w = 0; w < 8; w++) t += sred[w];
        sbcast = t;
    }
    __syncthreads();
    const float inv = 1.0f / sbcast;

    float o[8];
#pragma unroll
    for (int i = 0; i < 8; i++) o[i] = e[i] * inv;

    ((float4*)p)[tid]       = make_float4(o[0], o[1], o[2], o[3]);
    ((float4*)p)[tid + 256] = make_float4(o[4], o[5], o[6], o[7]);

    __half2* oh = (__half2*)(ah + row * (long long)LC);
    oh[2 * tid]           = __halves2half2(__float2half_rn(o[0]), __float2half_rn(o[1]));
    oh[2 * tid + 1]       = __halves2half2(__float2half_rn(o[2]), __float2half_rn(o[3]));
    oh[512 + 2 * tid]     = __halves2half2(__float2half_rn(o[4]), __float2half_rn(o[5]));
    oh[512 + 2 * tid + 1] = __halves2half2(__float2half_rn(o[6]), __float2half_rn(o[7]));
}

static void* dsym(const void* sym) { void* p = nullptr; cudaGetSymbolAddress(&p, sym); return p; }

extern "C" void kernel_launch(void* const* d_in, const int* in_sizes, int n_in,
                              void* d_out, int out_size)
{
    const float* query = (const float*)d_in[0];
    const float* bank  = (const float*)d_in[1];
    const float* Wc    = (const float*)d_in[2];
    const float* Woq   = (const float*)d_in[3];
    const float* Woc   = (const float*)d_in[4];

    float* out  = (float*)d_out;
    float* attn = out + (long long)BB * LQ * DD;

    __half* qh  = (__half*)dsym(g_qh);   __half* ql  = (__half*)dsym(g_ql);
    __half* bh  = (__half*)dsym(g_bh);   __half* bl  = (__half*)dsym(g_bl);
    __half* bTh = (__half*)dsym(g_bTh);
    __half* ch  = (__half*)dsym(g_ch);   __half* cl  = (__half*)dsym(g_cl);
    __half* ah  = (__half*)dsym(g_ah);
    __half* vh  = (__half*)dsym(g_vh);
    __half* wch = (__half*)dsym(g_wch);  __half* wcl = (__half*)dsym(g_wcl);
    __half* woqh= (__half*)dsym(g_woqh); __half* woql= (__half*)dsym(g_woql);
    __half* woch= (__half*)dsym(g_woch); __half* wocl= (__half*)dsym(g_wocl);

    // conversions
    split_f16<<<4096, 256>>>((const float4*)query, (__half2*)qh, (__half2*)ql, NQ_ELEMS / 4);
    split_f16<<<4096, 256>>>((const float4*)bank,  (__half2*)bh, (__half2*)bl, NB_ELEMS / 4);
    split_f16<<<1024, 256>>>((const float4*)Wc,  (__half2*)wch,  (__half2*)wcl,  NW_ELEMS / 4);
    split_f16<<<1024, 256>>>((const float4*)Woq, (__half2*)woqh, (__half2*)woql, NW_ELEMS / 4);
    split_f16<<<1024, 256>>>((const float4*)Woc, (__half2*)woch, (__half2*)wocl, NW_ELEMS / 4);
    transpose_h<<<dim3(DD / 32, LC / 32, BB), dim3(32, 8)>>>(bank, bTh);

    // G1: ctx = bank @ Wc^T, split-3, flat M=32768 -> split fp16 (ch, cl)
    {
        GemmArgs s = { bh, wch, bh, wcl, bl, wch };
        hgemm<1><<<dim3(DD / BN, (BB * LC) / BM, 1), 256>>>(
            s, 3, DD, nullptr, ch, cl, DD, 0LL, 0LL, 0LL, 1.0f);
    }
    // G2: score = (1/32) q @ ctx^T, split-3, per-batch -> attn fp32
    {
        GemmArgs s = { qh, ch, qh, cl, ql, ch };
        hgemm<0><<<dim3(LC / BN, LQ / BM, BB), 256>>>(
            s, 3, DD, attn, nullptr, nullptr, LC,
            (long long)LQ * DD, (long long)LC * DD, (long long)LQ * LC, 0.03125f);
    }
    // softmax in place + fp16 emit
    softmax_emit<<<BB * LQ, 256>>>(attn, ah);

    // G3: context = attn @ bankT^T, single, per-batch -> fp16 (vh)
    {
        GemmArgs s = { ah, bTh, nullptr, nullptr, nullptr, nullptr };
        hgemm<2><<<dim3(DD / BN, LQ / BM, BB), 256>>>(
            s, 1, LC, nullptr, vh, nullptr, DD,
            (long long)LQ * LC, (long long)DD * LC, (long long)LQ * DD, 1.0f);
    }
    // G4: out = context @ Woc^T + q @ Woq^T, 2 segments, flat M=32768 -> fp32
    {
        GemmArgs s = { vh, woch, qh, woqh, nullptr, nullptr };
        hgemm<0><<<dim3(DD / BN, (BB * LQ) / BM, 1), 256>>>(
            s, 2, DD, out, nullptr, nullptr, DD, 0LL, 0LL, 0LL, 1.0f);
    }
}

// round 6
// speedup vs baseline: 3.4507x; 1.0731x over previous
#include <cuda_runtime.h>
#include <cuda_fp16.h>
#include <math.h>
#include <stdint.h>

#define BB 16
#define LQ 2048
#define LC 2048
#define DD 1024
#define NQ_ELEMS  (BB * LQ * DD)
#define NB_ELEMS  (BB * LC * DD)
#define NW_ELEMS  (DD * DD)
#define NA_ELEMS  ((long long)BB * LQ * LC)

// scratch
__device__ __half g_qh[NQ_ELEMS], g_ql[NQ_ELEMS];
__device__ __half g_bh[NB_ELEMS], g_bl[NB_ELEMS];
__device__ __half g_bTh[NB_ELEMS];
__device__ __half g_ch[NB_ELEMS], g_cl[NB_ELEMS];
__device__ __half g_ah[NA_ELEMS];
__device__ __half g_vh[NQ_ELEMS];
__device__ __half g_wch[NW_ELEMS], g_wcl[NW_ELEMS];
__device__ __half g_woqh[NW_ELEMS], g_woql[NW_ELEMS];
__device__ __half g_woch[NW_ELEMS], g_wocl[NW_ELEMS];

// ---- helpers ----
__device__ __forceinline__ uint32_t smem_u32(const void* p) {
    uint32_t a;
    asm("{ .reg .u64 t; cvta.to.shared.u64 t, %1; cvt.u32.u64 %0, t; }" : "=r"(a) : "l"(p));
    return a;
}
__device__ __forceinline__ void cp16(uint32_t dst, const void* src) {
    asm volatile("cp.async.cg.shared.global [%0], [%1], 16;" :: "r"(dst), "l"(src) : "memory");
}
__device__ __forceinline__ void cp_commit() { asm volatile("cp.async.commit_group;" ::: "memory"); }
template <int N> __device__ __forceinline__ void cp_wait() {
    asm volatile("cp.async.wait_group %0;" :: "n"(N) : "memory");
}
__device__ __forceinline__ void ldm4(uint32_t* r, uint32_t addr) {
    asm volatile("ldmatrix.sync.aligned.m8n8.x4.shared.b16 {%0,%1,%2,%3}, [%4];"
                 : "=r"(r[0]), "=r"(r[1]), "=r"(r[2]), "=r"(r[3]) : "r"(addr));
}
__device__ __forceinline__ void mma16816(float* c, const uint32_t* a, const uint32_t* b) {
    asm volatile("mma.sync.aligned.m16n8k16.row.col.f32.f16.f16.f32 "
                 "{%0,%1,%2,%3},{%4,%5,%6,%7},{%8,%9},{%0,%1,%2,%3};"
                 : "+f"(c[0]), "+f"(c[1]), "+f"(c[2]), "+f"(c[3])
                 : "r"(a[0]), "r"(a[1]), "r"(a[2]), "r"(a[3]), "r"(b[0]), "r"(b[1]));
}

// ---- HMMA GEMM: C[M,N] = alpha * sum_seg A_s @ B_s^T ----
// A_s: [M,K] row-major fp16; B_s: [N,K] row-major fp16.
#define BM 128
#define BN 256
#define BK 64
#define STRD 72                    // BK + 8 pad (halfwords)
#define SA_BYTES (BM * STRD * 2)   // 18432
#define SB_BYTES (BN * STRD * 2)   // 36864
#define STAGE_BYTES (SA_BYTES + SB_BYTES)
#define NSTAGE 3
#define SMEM_DYN (NSTAGE * STAGE_BYTES)

struct GemmArgs {
    const __half *a0, *b0, *a1, *b1, *a2, *b2;
};

template <int MODE>  // 0: fp32 out; 1: split fp16 out (Ch,Cl); 2: single fp16 out (Ch)
__global__ void __launch_bounds__(256)
hgemm(GemmArgs seg, int nseg, int K,
      float* __restrict__ Cf, __half* __restrict__ Ch, __half* __restrict__ Cl,
      int ldc, long long sA, long long sB, long long sC, float alpha)
{
    extern __shared__ char dynsmem[];
    const uint32_t base0 = smem_u32(dynsmem);

    const int tid = threadIdx.x, lane = tid & 31, wid = tid >> 5;
    const int warp_m = wid & 1, warp_n = wid >> 1;   // 2 x 4 warp grid -> 64x64 per warp
    const int bm = blockIdx.y, bn = blockIdx.x, bz = blockIdx.z;

    const __half* Aseg[3] = { seg.a0, seg.a1, seg.a2 };
    const __half* Bseg[3] = { seg.b0, seg.b1, seg.b2 };

    const int tps = K / BK;
    const int CT = nseg * tps;

    float acc[4][8][4];
#pragma unroll
    for (int i = 0; i < 4; i++)
#pragma unroll
        for (int j = 0; j < 8; j++)
#pragma unroll
            for (int q = 0; q < 4; q++) acc[i][j][q] = 0.0f;

    // loaders: A 1024 chunks (4/thread), B 2048 chunks (8/thread); chunk=16B=8 halfwords
    auto load_tile = [&](int t, int buf) {
        const int s = t / tps, kk = (t - s * tps) * BK;
        const __half* Ab = Aseg[s] + bz * sA + (long long)(bm * BM) * K + kk;
        const __half* Bb = Bseg[s] + bz * sB + (long long)(bn * BN) * K + kk;
        const uint32_t sa = base0 + buf * STAGE_BYTES;
        const uint32_t sb = sa + SA_BYTES;
#pragma unroll
        for (int i = 0; i < 4; i++) {
            const int c = tid + (i << 8);
            const int row = c >> 3, off = (c & 7) * 8;
            cp16(sa + (uint32_t)(row * STRD + off) * 2, Ab + (long long)row * K + off);
        }
#pragma unroll
        for (int i = 0; i < 8; i++) {
            const int c = tid + (i << 8);
            const int row = c >> 3, off = (c & 7) * 8;
            cp16(sb + (uint32_t)(row * STRD + off) * 2, Bb + (long long)row * K + off);
        }
        cp_commit();
    };

    // ldmatrix per-thread byte offsets (within a stage's A / B region)
    const uint32_t a_base = (uint32_t)(((warp_m * 64 + (lane & 15)) * STRD + (lane >> 4) * 8) * 2);
    uint32_t b_base[4];
#pragma unroll
    for (int nf = 0; nf < 4; nf++)
        b_base[nf] = (uint32_t)(((warp_n * 64 + nf * 16 + ((lane >> 4) << 3) + (lane & 7)) * STRD
                                 + ((lane >> 3) & 1) * 8) * 2);

    load_tile(0, 0);
    if (CT > 1) load_tile(1, 1); else cp_commit();

    for (int t = 0; t < CT; ++t) {
        cp_wait<1>();
        __syncthreads();
        if (t + 2 < CT) load_tile(t + 2, (t + 2) % NSTAGE); else cp_commit();

        const uint32_t sa = base0 + (t % NSTAGE) * STAGE_BYTES;
        const uint32_t sb = sa + SA_BYTES;
#pragma unroll
        for (int kk = 0; kk < 4; kk++) {
            const uint32_t kadd = kk * 32;   // 16 halfwords
            uint32_t a[4][4], b[8][2];
#pragma unroll
            for (int im = 0; im < 4; im++)
                ldm4(a[im], sa + a_base + (uint32_t)(im * 16 * STRD * 2) + kadd);
#pragma unroll
            for (int nf = 0; nf < 4; nf++) {
                uint32_t r[4];
                ldm4(r, sb + b_base[nf] + kadd);
                b[2 * nf][0] = r[0]; b[2 * nf][1] = r[1];
                b[2 * nf + 1][0] = r[2]; b[2 * nf + 1][1] = r[3];
            }
#pragma unroll
            for (int im = 0; im < 4; im++)
#pragma unroll
                for (int in = 0; in < 8; in++)
                    mma16816(acc[im][in], a[im], b[in]);
        }
    }

    // epilogue
    const int gr = lane >> 2, qd = lane & 3;
#pragma unroll
    for (int im = 0; im < 4; im++) {
#pragma unroll
        for (int in = 0; in < 8; in++) {
            const long long row0 = (long long)bm * BM + warp_m * 64 + im * 16 + gr;
            const int col = bn * BN + warp_n * 64 + in * 8 + qd * 2;
#pragma unroll
            for (int h = 0; h < 2; h++) {
                const long long row = row0 + h * 8;
                const float v0 = alpha * acc[im][in][2 * h + 0];
                const float v1 = alpha * acc[im][in][2 * h + 1];
                if (MODE == 0) {
                    *(float2*)(Cf + bz * sC + row * ldc + col) = make_float2(v0, v1);
                } else if (MODE == 1) {
                    const __half h0 = __float2half_rn(v0), h1 = __float2half_rn(v1);
                    const __half l0 = __float2half_rn(v0 - __half2float(h0));
                    const __half l1 = __float2half_rn(v1 - __half2float(h1));
                    *(__half2*)(Ch + bz * sC + row * ldc + col) = __halves2half2(h0, h1);
                    *(__half2*)(Cl + bz * sC + row * ldc + col) = __halves2half2(l0, l1);
                } else {
                    *(__half2*)(Ch + bz * sC + row * ldc + col) =
                        __halves2half2(__float2half_rn(v0), __float2half_rn(v1));
                }
            }
        }
    }
}

// ---- fp32 -> fp16 hi/lo split ----
__global__ void __launch_bounds__(256)
split_f16(const float4* __restrict__ src, __half2* __restrict__ hi, __half2* __restrict__ lo, int n4)
{
    for (int i = blockIdx.x * blockDim.x + threadIdx.x; i < n4; i += gridDim.x * blockDim.x) {
        const float4 v = src[i];
        const __half hx = __float2half_rn(v.x), hy = __float2half_rn(v.y);
        const __half hz = __float2half_rn(v.z), hw = __float2half_rn(v.w);
        hi[2 * i]     = __halves2half2(hx, hy);
        hi[2 * i + 1] = __halves2half2(hz, hw);
        lo[2 * i]     = __halves2half2(__float2half_rn(v.x - __half2float(hx)),
                                       __float2half_rn(v.y - __half2float(hy)));
        lo[2 * i + 1] = __halves2half2(__float2half_rn(v.z - __half2float(hz)),
                                       __float2half_rn(v.w - __half2float(hw)));
    }
}

// ---- bank [b,K,D] fp32 -> bankT [b,D,K] fp16 ----
__global__ void __launch_bounds__(256)
transpose_h(const float* __restrict__ src, __half* __restrict__ dst)
{
    __shared__ float t[32][33];
    const int tx = threadIdx.x, ty = threadIdx.y;       // (32, 8)
    const int kb = blockIdx.y, db = blockIdx.x, b = blockIdx.z;
    const float* s = src + (long long)b * LC * DD;
#pragma unroll
    for (int r = 0; r < 4; r++)
        t[ty + r * 8][tx] = s[(long long)(kb * 32 + ty + r * 8) * DD + db * 32 + tx];
    __syncthreads();
    __half* o = dst + (long long)b * DD * LC;
#pragma unroll
    for (int r = 0; r < 4; r++) {
        const int drow = db * 32 + ty + r * 8;
        const int kcol = kb * 32 + tx;
        o[(long long)drow * LC + kcol] = __float2half_rn(t[tx][ty + r * 8]);
    }
}

// ---- softmax (fp32 in/out in place) + fp16 emit ----
__global__ void __launch_bounds__(256)
softmax_emit(float* __restrict__ data, __half* __restrict__ ah)
{
    const long long row = blockIdx.x;
    float* p = data + row * (long long)LC;
    const int tid = threadIdx.x;
    const int lane = tid & 31, wid = tid >> 5;
    __shared__ float sred[8];
    __shared__ float sbcast;

    float4 x0 = ((const float4*)p)[tid];
    float4 x1 = ((const float4*)p)[tid + 256];

    float m = fmaxf(fmaxf(fmaxf(x0.x, x0.y), fmaxf(x0.z, x0.w)),
                    fmaxf(fmaxf(x1.x, x1.y), fmaxf(x1.z, x1.w)));
#pragma unroll
    for (int off = 16; off; off >>= 1) m = fmaxf(m, __shfl_xor_sync(0xffffffffu, m, off));
    if (lane == 0) sred[wid] = m;
    __syncthreads();
    if (tid == 0) {
        float t = sred[0];
#pragma unroll
        for (int w = 1; w < 8; w++) t = fmaxf(t, sred[w]);
        sbcast = t;
    }
    __syncthreads();
    const float rowmax = sbcast;
    __syncthreads();

    float e[8];
    e[0] = expf(x0.x - rowmax); e[1] = expf(x0.y - rowmax);
    e[2] = expf(x0.z - rowmax); e[3] = expf(x0.w - rowmax);
    e[4] = expf(x1.x - rowmax); e[5] = expf(x1.y - rowmax);
    e[6] = expf(x1.z - rowmax); e[7] = expf(x1.w - rowmax);

    float ssum = 0.0f;
#pragma unroll
    for (int i = 0; i < 8; i++) ssum += e[i];
#pragma unroll
    for (int off = 16; off; off >>= 1) ssum += __shfl_xor_sync(0xffffffffu, ssum, off);
    if (lane == 0) sred[wid] = ssum;
    __syncthreads();
    if (tid == 0) {
        float t = 0.0f;
#pragma unroll
        for (int w = 0; w < 8; w++) t += sred[w];
        sbcast = t;
    }
    __syncthreads();
    const float inv = 1.0f / sbcast;

    float o[8];
#pragma unroll
    for (int i = 0; i < 8; i++) o[i] = e[i] * inv;

    ((float4*)p)[tid]       = make_float4(o[0], o[1], o[2], o[3]);
    ((float4*)p)[tid + 256] = make_float4(o[4], o[5], o[6], o[7]);

    __half2* oh = (__half2*)(ah + row * (long long)LC);
    oh[2 * tid]           = __halves2half2(__float2half_rn(o[0]), __float2half_rn(o[1]));
    oh[2 * tid + 1]       = __halves2half2(__float2half_rn(o[2]), __float2half_rn(o[3]));
    oh[512 + 2 * tid]     = __halves2half2(__float2half_rn(o[4]), __float2half_rn(o[5]));
    oh[512 + 2 * tid + 1] = __halves2half2(__float2half_rn(o[6]), __float2half_rn(o[7]));
}

static void* dsym(const void* sym) { void* p = nullptr; cudaGetSymbolAddress(&p, sym); return p; }

extern "C" void kernel_launch(void* const* d_in, const int* in_sizes, int n_in,
                              void* d_out, int out_size)
{
    const float* query = (const float*)d_in[0];
    const float* bank  = (const float*)d_in[1];
    const float* Wc    = (const float*)d_in[2];
    const float* Woq   = (const float*)d_in[3];
    const float* Woc   = (const float*)d_in[4];

    float* out  = (float*)d_out;
    float* attn = out + (long long)BB * LQ * DD;

    __half* qh  = (__half*)dsym(g_qh);   __half* ql  = (__half*)dsym(g_ql);
    __half* bh  = (__half*)dsym(g_bh);   __half* bl  = (__half*)dsym(g_bl);
    __half* bTh = (__half*)dsym(g_bTh);
    __half* ch  = (__half*)dsym(g_ch);   __half* cl  = (__half*)dsym(g_cl);
    __half* ah  = (__half*)dsym(g_ah);
    __half* vh  = (__half*)dsym(g_vh);
    __half* wch = (__half*)dsym(g_wch);  __half* wcl = (__half*)dsym(g_wcl);
    __half* woqh= (__half*)dsym(g_woqh); __half* woql= (__half*)dsym(g_woql);
    __half* woch= (__half*)dsym(g_woch); __half* wocl= (__half*)dsym(g_wocl);

    cudaFuncSetAttribute(hgemm<0>, cudaFuncAttributeMaxDynamicSharedMemorySize, SMEM_DYN);
    cudaFuncSetAttribute(hgemm<1>, cudaFuncAttributeMaxDynamicSharedMemorySize, SMEM_DYN);
    cudaFuncSetAttribute(hgemm<2>, cudaFuncAttributeMaxDynamicSharedMemorySize, SMEM_DYN);

    // conversions
    split_f16<<<4096, 256>>>((const float4*)query, (__half2*)qh, (__half2*)ql, NQ_ELEMS / 4);
    split_f16<<<4096, 256>>>((const float4*)bank,  (__half2*)bh, (__half2*)bl, NB_ELEMS / 4);
    split_f16<<<1024, 256>>>((const float4*)Wc,  (__half2*)wch,  (__half2*)wcl,  NW_ELEMS / 4);
    split_f16<<<1024, 256>>>((const float4*)Woq, (__half2*)woqh, (__half2*)woql, NW_ELEMS / 4);
    split_f16<<<1024, 256>>>((const float4*)Woc, (__half2*)woch, (__half2*)wocl, NW_ELEMS / 4);
    transpose_h<<<dim3(DD / 32, LC / 32, BB), dim3(32, 8)>>>(bank, bTh);

    // G1: ctx = bank @ Wc^T, split-3, flat M=32768 -> split fp16 (ch, cl)
    {
        GemmArgs s = { bh, wch, bh, wcl, bl, wch };
        hgemm<1><<<dim3(DD / BN, (BB * LC) / BM, 1), 256, SMEM_DYN>>>(
            s, 3, DD, nullptr, ch, cl, DD, 0LL, 0LL, 0LL, 1.0f);
    }
    // G2: score = (1/32) q @ ctx^T, split-3, per-batch -> attn fp32
    {
        GemmArgs s = { qh, ch, qh, cl, ql, ch };
        hgemm<0><<<dim3(LC / BN, LQ / BM, BB), 256, SMEM_DYN>>>(
            s, 3, DD, attn, nullptr, nullptr, LC,
            (long long)LQ * DD, (long long)LC * DD, (long long)LQ * LC, 0.03125f);
    }
    // softmax in place + fp16 emit
    softmax_emit<<<BB * LQ, 256>>>(attn, ah);

    // G3: context = attn @ bankT^T, single, per-batch -> fp16 (vh)
    {
        GemmArgs s = { ah, bTh, nullptr, nullptr, nullptr, nullptr };
        hgemm<2><<<dim3(DD / BN, LQ / BM, BB), 256, SMEM_DYN>>>(
            s, 1, LC, nullptr, vh, nullptr, DD,
            (long long)LQ * LC, (long long)DD * LC, (long long)LQ * DD, 1.0f);
    }
    // G4: out = context @ Woc^T + q @ Woq^T, 2 segments, flat M=32768 -> fp32
    {
        GemmArgs s = { vh, woch, qh, woqh, nullptr, nullptr };
        hgemm<0><<<dim3(DD / BN, (BB * LQ) / BM, 1), 256, SMEM_DYN>>>(
            s, 2, DD, out, nullptr, nullptr, DD, 0LL, 0LL, 0LL, 1.0f);
    }
}

// round 7
// speedup vs baseline: 4.8602x; 1.4085x over previous
#include <cuda_runtime.h>
#include <cuda_fp16.h>
#include <math.h>
#include <stdint.h>

#define BB 16
#define LQ 2048
#define LC 2048
#define DD 1024
#define NQ_ELEMS  (BB * LQ * DD)
#define NB_ELEMS  (BB * LC * DD)
#define NW_ELEMS  (DD * DD)
#define NA_ELEMS  ((long long)BB * LQ * LC)

// scratch
__device__ __half g_qh[NQ_ELEMS], g_ql[NQ_ELEMS];
__device__ __half g_bh[NB_ELEMS], g_bl[NB_ELEMS];
__device__ __half g_bTh[NB_ELEMS];
__device__ __half g_ch[NB_ELEMS], g_cl[NB_ELEMS];
__device__ __half g_ah[NA_ELEMS];
__device__ __half g_vh[NQ_ELEMS];
__device__ __half g_wch[NW_ELEMS], g_wcl[NW_ELEMS];
__device__ __half g_woqh[NW_ELEMS], g_woql[NW_ELEMS];
__device__ __half g_woch[NW_ELEMS], g_wocl[NW_ELEMS];

// ---- helpers ----
__device__ __forceinline__ uint32_t smem_u32(const void* p) {
    uint32_t a;
    asm("{ .reg .u64 t; cvta.to.shared.u64 t, %1; cvt.u32.u64 %0, t; }" : "=r"(a) : "l"(p));
    return a;
}
__device__ __forceinline__ void cp16(uint32_t dst, const void* src) {
    asm volatile("cp.async.cg.shared.global [%0], [%1], 16;" :: "r"(dst), "l"(src) : "memory");
}
__device__ __forceinline__ void cp_commit() { asm volatile("cp.async.commit_group;" ::: "memory"); }
template <int N> __device__ __forceinline__ void cp_wait() {
    asm volatile("cp.async.wait_group %0;" :: "n"(N) : "memory");
}
__device__ __forceinline__ void ldm4(uint32_t* r, uint32_t addr) {
    asm volatile("ldmatrix.sync.aligned.m8n8.x4.shared.b16 {%0,%1,%2,%3}, [%4];"
                 : "=r"(r[0]), "=r"(r[1]), "=r"(r[2]), "=r"(r[3]) : "r"(addr));
}
__device__ __forceinline__ void mma16816(float* c, const uint32_t* a, const uint32_t* b) {
    asm volatile("mma.sync.aligned.m16n8k16.row.col.f32.f16.f16.f32 "
                 "{%0,%1,%2,%3},{%4,%5,%6,%7},{%8,%9},{%0,%1,%2,%3};"
                 : "+f"(c[0]), "+f"(c[1]), "+f"(c[2]), "+f"(c[3])
                 : "r"(a[0]), "r"(a[1]), "r"(a[2]), "r"(a[3]), "r"(b[0]), "r"(b[1]));
}

// ---- HMMA GEMM: C[M,N] = alpha * sum_seg A_s @ B_s^T ----
#define BM 128
#define BN 256
#define BK 64
#define STRD 72                    // BK + 8 pad (halfwords)
#define SA_BYTES (BM * STRD * 2)
#define SB_BYTES (BN * STRD * 2)
#define STAGE_BYTES (SA_BYTES + SB_BYTES)
#define NSTAGE 3
#define SMEM_DYN (NSTAGE * STAGE_BYTES)

struct GemmArgs {
    const __half *a0, *b0, *a1, *b1, *a2, *b2;
};

template <int MODE>  // 0: fp32 out; 1: split fp16 out (Ch,Cl); 2: single fp16 out (Ch)
__global__ void __launch_bounds__(256)
hgemm(GemmArgs seg, int nseg, int K,
      float* __restrict__ Cf, __half* __restrict__ Ch, __half* __restrict__ Cl,
      int ldc, long long sA, long long sB, long long sC, float alpha)
{
    extern __shared__ char dynsmem[];
    const uint32_t base0 = smem_u32(dynsmem);

    const int tid = threadIdx.x, lane = tid & 31, wid = tid >> 5;
    const int warp_m = wid & 1, warp_n = wid >> 1;   // 2x4 warps -> 64x64 per warp
    const int bm = blockIdx.y, bn = blockIdx.x, bz = blockIdx.z;

    const __half* Aseg[3] = { seg.a0, seg.a1, seg.a2 };
    const __half* Bseg[3] = { seg.b0, seg.b1, seg.b2 };

    const int tps = K / BK;
    const int CT = nseg * tps;

    float acc[4][8][4];
#pragma unroll
    for (int i = 0; i < 4; i++)
#pragma unroll
        for (int j = 0; j < 8; j++)
#pragma unroll
            for (int q = 0; q < 4; q++) acc[i][j][q] = 0.0f;

    // loader constants: chunk = 16B = 8 halfwords
    const int lrow = tid >> 3, loff = (tid & 7) * 8;

    auto load_tile = [&](int t, int buf) {
        const int s = t / tps, kk = (t - s * tps) * BK;
        const __half* Ab = Aseg[s] + bz * sA + (long long)(bm * BM) * K + kk;
        const __half* Bb = Bseg[s] + bz * sB + (long long)(bn * BN) * K + kk;
        const uint32_t sa = base0 + buf * STAGE_BYTES;
        const uint32_t sb = sa + SA_BYTES;
#pragma unroll
        for (int i = 0; i < 4; i++) {
            const int row = lrow + i * 32;
            cp16(sa + (uint32_t)(row * STRD + loff) * 2, Ab + (long long)row * K + loff);
        }
#pragma unroll
        for (int i = 0; i < 8; i++) {
            const int row = lrow + i * 32;
            cp16(sb + (uint32_t)(row * STRD + loff) * 2, Bb + (long long)row * K + loff);
        }
        cp_commit();
    };

    // ldmatrix per-thread byte offsets
    const uint32_t a_base = (uint32_t)(((warp_m * 64 + (lane & 15)) * STRD + (lane >> 4) * 8) * 2);
    uint32_t b_base[4];
#pragma unroll
    for (int nf = 0; nf < 4; nf++)
        b_base[nf] = (uint32_t)(((warp_n * 64 + nf * 16 + ((lane >> 4) << 3) + (lane & 7)) * STRD
                                 + ((lane >> 3) & 1) * 8) * 2);

    // register fragment double buffers
    uint32_t afr[2][4][4], bfr[2][8][2];
    auto ldfrag = [&](int buf, uint32_t sa, int kk) {
        const uint32_t sb = sa + SA_BYTES;
        const uint32_t kadd = (uint32_t)kk * 32;
#pragma unroll
        for (int im = 0; im < 4; im++)
            ldm4(afr[buf][im], sa + a_base + (uint32_t)(im * 16 * STRD * 2) + kadd);
#pragma unroll
        for (int nf = 0; nf < 4; nf++) {
            uint32_t r[4];
            ldm4(r, sb + b_base[nf] + kadd);
            bfr[buf][2 * nf][0] = r[0];     bfr[buf][2 * nf][1] = r[1];
            bfr[buf][2 * nf + 1][0] = r[2]; bfr[buf][2 * nf + 1][1] = r[3];
        }
    };

    load_tile(0, 0);
    if (CT > 1) load_tile(1, 1); else cp_commit();
    cp_wait<1>();
    __syncthreads();

    int cur = 0;
    ldfrag(0, base0, 0);   // tile 0, kstep 0

    for (int t = 0; t < CT; ++t) {
        const uint32_t sa_t = base0 + (t % NSTAGE) * STAGE_BYTES;
        if (t + 2 < CT) load_tile(t + 2, (t + 2) % NSTAGE); else cp_commit();

#pragma unroll
        for (int kk = 0; kk < 4; kk++) {
            if (kk < 3) ldfrag(cur ^ 1, sa_t, kk + 1);
#pragma unroll
            for (int im = 0; im < 4; im++)
#pragma unroll
                for (int in = 0; in < 8; in++)
                    mma16816(acc[im][in], afr[cur][im], bfr[cur][in]);
            cur ^= 1;
        }

        cp_wait<1>();
        __syncthreads();
        if (t + 1 < CT)
            ldfrag(cur, base0 + ((t + 1) % NSTAGE) * STAGE_BYTES, 0);
    }

    // epilogue
    const int gr = lane >> 2, qd = lane & 3;
#pragma unroll
    for (int im = 0; im < 4; im++) {
#pragma unroll
        for (int in = 0; in < 8; in++) {
            const long long row0 = (long long)bm * BM + warp_m * 64 + im * 16 + gr;
            const int col = bn * BN + warp_n * 64 + in * 8 + qd * 2;
#pragma unroll
            for (int h = 0; h < 2; h++) {
                const long long row = row0 + h * 8;
                const float v0 = alpha * acc[im][in][2 * h + 0];
                const float v1 = alpha * acc[im][in][2 * h + 1];
                if (MODE == 0) {
                    *(float2*)(Cf + bz * sC + row * ldc + col) = make_float2(v0, v1);
                } else if (MODE == 1) {
                    const __half h0 = __float2half_rn(v0), h1 = __float2half_rn(v1);
                    const __half l0 = __float2half_rn(v0 - __half2float(h0));
                    const __half l1 = __float2half_rn(v1 - __half2float(h1));
                    *(__half2*)(Ch + bz * sC + row * ldc + col) = __halves2half2(h0, h1);
                    *(__half2*)(Cl + bz * sC + row * ldc + col) = __halves2half2(l0, l1);
                } else {
                    *(__half2*)(Ch + bz * sC + row * ldc + col) =
                        __halves2half2(__float2half_rn(v0), __float2half_rn(v1));
                }
            }
        }
    }
}

// ---- fp32 -> fp16 hi/lo split ----
__global__ void __launch_bounds__(256)
split_f16(const float4* __restrict__ src, __half2* __restrict__ hi, __half2* __restrict__ lo, int n4)
{
    for (int i = blockIdx.x * blockDim.x + threadIdx.x; i < n4; i += gridDim.x * blockDim.x) {
        const float4 v = src[i];
        const __half hx = __float2half_rn(v.x), hy = __float2half_rn(v.y);
        const __half hz = __float2half_rn(v.z), hw = __float2half_rn(v.w);
        hi[2 * i]     = __halves2half2(hx, hy);
        hi[2 * i + 1] = __halves2half2(hz, hw);
        lo[2 * i]     = __halves2half2(__float2half_rn(v.x - __half2float(hx)),
                                       __float2half_rn(v.y - __half2float(hy)));
        lo[2 * i + 1] = __halves2half2(__float2half_rn(v.z - __half2float(hz)),
                                       __float2half_rn(v.w - __half2float(hw)));
    }
}

// ---- bank [b,K,D] fp32 -> bankT [b,D,K] fp16 ----
__global__ void __launch_bounds__(256)
transpose_h(const float* __restrict__ src, __half* __restrict__ dst)
{
    __shared__ float t[32][33];
    const int tx = threadIdx.x, ty = threadIdx.y;       // (32, 8)
    const int kb = blockIdx.y, db = blockIdx.x, b = blockIdx.z;
    const float* s = src + (long long)b * LC * DD;
#pragma unroll
    for (int r = 0; r < 4; r++)
        t[ty + r * 8][tx] = s[(long long)(kb * 32 + ty + r * 8) * DD + db * 32 + tx];
    __syncthreads();
    __half* o = dst + (long long)b * DD * LC;
#pragma unroll
    for (int r = 0; r < 4; r++) {
        const int drow = db * 32 + ty + r * 8;
        const int kcol = kb * 32 + tx;
        o[(long long)drow * LC + kcol] = __float2half_rn(t[tx][ty + r * 8]);
    }
}

// ---- softmax (fp32 in/out in place) + fp16 emit ----
__global__ void __launch_bounds__(256)
softmax_emit(float* __restrict__ data, __half* __restrict__ ah)
{
    const long long row = blockIdx.x;
    float* p = data + row * (long long)LC;
    const int tid = threadIdx.x;
    const int lane = tid & 31, wid = tid >> 5;
    __shared__ float sred[8];
    __shared__ float sbcast;

    float4 x0 = ((const float4*)p)[tid];
    float4 x1 = ((const float4*)p)[tid + 256];

    float m = fmaxf(fmaxf(fmaxf(x0.x, x0.y), fmaxf(x0.z, x0.w)),
                    fmaxf(fmaxf(x1.x, x1.y), fmaxf(x1.z, x1.w)));
#pragma unroll
    for (int off = 16; off; off >>= 1) m = fmaxf(m, __shfl_xor_sync(0xffffffffu, m, off));
    if (lane == 0) sred[wid] = m;
    __syncthreads();
    if (tid == 0) {
        float t = sred[0];
#pragma unroll
        for (int w = 1; w < 8; w++) t = fmaxf(t, sred[w]);
        sbcast = t;
    }
    __syncthreads();
    const float rowmax = sbcast;
    __syncthreads();

    float e[8];
    e[0] = expf(x0.x - rowmax); e[1] = expf(x0.y - rowmax);
    e[2] = expf(x0.z - rowmax); e[3] = expf(x0.w - rowmax);
    e[4] = expf(x1.x - rowmax); e[5] = expf(x1.y - rowmax);
    e[6] = expf(x1.z - rowmax); e[7] = expf(x1.w - rowmax);

    float ssum = 0.0f;
#pragma unroll
    for (int i = 0; i < 8; i++) ssum += e[i];
#pragma unroll
    for (int off = 16; off; off >>= 1) ssum += __shfl_xor_sync(0xffffffffu, ssum, off);
    if (lane == 0) sred[wid] = ssum;
    __syncthreads();
    if (tid == 0) {
        float t = 0.0f;
#pragma unroll
        for (int w = 0; w < 8; w++) t += sred[w];
        sbcast = t;
    }
    __syncthreads();
    const float inv = 1.0f / sbcast;

    float o[8];
#pragma unroll
    for (int i = 0; i < 8; i++) o[i] = e[i] * inv;

    ((float4*)p)[tid]       = make_float4(o[0], o[1], o[2], o[3]);
    ((float4*)p)[tid + 256] = make_float4(o[4], o[5], o[6], o[7]);

    __half2* oh = (__half2*)(ah + row * (long long)LC);
    oh[2 * tid]           = __halves2half2(__float2half_rn(o[0]), __float2half_rn(o[1]));
    oh[2 * tid + 1]       = __halves2half2(__float2half_rn(o[2]), __float2half_rn(o[3]));
    oh[512 + 2 * tid]     = __halves2half2(__float2half_rn(o[4]), __float2half_rn(o[5]));
    oh[512 + 2 * tid + 1] = __halves2half2(__float2half_rn(o[6]), __float2half_rn(o[7]));
}

static void* dsym(const void* sym) { void* p = nullptr; cudaGetSymbolAddress(&p, sym); return p; }

extern "C" void kernel_launch(void* const* d_in, const int* in_sizes, int n_in,
                              void* d_out, int out_size)
{
    const float* query = (const float*)d_in[0];
    const float* bank  = (const float*)d_in[1];
    const float* Wc    = (const float*)d_in[2];
    const float* Woq   = (const float*)d_in[3];
    const float* Woc   = (const float*)d_in[4];

    float* out  = (float*)d_out;
    float* attn = out + (long long)BB * LQ * DD;

    __half* qh  = (__half*)dsym(g_qh);   __half* ql  = (__half*)dsym(g_ql);
    __half* bh  = (__half*)dsym(g_bh);   __half* bl  = (__half*)dsym(g_bl);
    __half* bTh = (__half*)dsym(g_bTh);
    __half* ch  = (__half*)dsym(g_ch);   __half* cl  = (__half*)dsym(g_cl);
    __half* ah  = (__half*)dsym(g_ah);
    __half* vh  = (__half*)dsym(g_vh);
    __half* wch = (__half*)dsym(g_wch);  __half* wcl = (__half*)dsym(g_wcl);
    __half* woqh= (__half*)dsym(g_woqh); __half* woql= (__half*)dsym(g_woql);
    __half* woch= (__half*)dsym(g_woch); __half* wocl= (__half*)dsym(g_wocl);

    cudaFuncSetAttribute(hgemm<0>, cudaFuncAttributeMaxDynamicSharedMemorySize, SMEM_DYN);
    cudaFuncSetAttribute(hgemm<1>, cudaFuncAttributeMaxDynamicSharedMemorySize, SMEM_DYN);
    cudaFuncSetAttribute(hgemm<2>, cudaFuncAttributeMaxDynamicSharedMemorySize, SMEM_DYN);

    split_f16<<<4096, 256>>>((const float4*)query, (__half2*)qh, (__half2*)ql, NQ_ELEMS / 4);
    split_f16<<<4096, 256>>>((const float4*)bank,  (__half2*)bh, (__half2*)bl, NB_ELEMS / 4);
    split_f16<<<1024, 256>>>((const float4*)Wc,  (__half2*)wch,  (__half2*)wcl,  NW_ELEMS / 4);
    split_f16<<<1024, 256>>>((const float4*)Woq, (__half2*)woqh, (__half2*)woql, NW_ELEMS / 4);
    split_f16<<<1024, 256>>>((const float4*)Woc, (__half2*)woch, (__half2*)wocl, NW_ELEMS / 4);
    transpose_h<<<dim3(DD / 32, LC / 32, BB), dim3(32, 8)>>>(bank, bTh);

    // G1: ctx = bank @ Wc^T, split-3 -> split fp16 (ch, cl)
    {
        GemmArgs s = { bh, wch, bh, wcl, bl, wch };
        hgemm<1><<<dim3(DD / BN, (BB * LC) / BM, 1), 256, SMEM_DYN>>>(
            s, 3, DD, nullptr, ch, cl, DD, 0LL, 0LL, 0LL, 1.0f);
    }
    // G2: score = (1/32) q @ ctx^T, split-3 -> attn fp32
    {
        GemmArgs s = { qh, ch, qh, cl, ql, ch };
        hgemm<0><<<dim3(LC / BN, LQ / BM, BB), 256, SMEM_DYN>>>(
            s, 3, DD, attn, nullptr, nullptr, LC,
            (long long)LQ * DD, (long long)LC * DD, (long long)LQ * LC, 0.03125f);
    }
    softmax_emit<<<BB * LQ, 256>>>(attn, ah);

    // G3: context = attn @ bankT^T, single -> fp16 (vh)
    {
        GemmArgs s = { ah, bTh, nullptr, nullptr, nullptr, nullptr };
        hgemm<2><<<dim3(DD / BN, LQ / BM, BB), 256, SMEM_DYN>>>(
            s, 1, LC, nullptr, vh, nullptr, DD,
            (long long)LQ * LC, (long long)DD * LC, (long long)LQ * DD, 1.0f);
    }
    // G4: out = context @ Woc^T + q @ Woq^T, 2 segments -> fp32
    {
        GemmArgs s = { vh, woch, qh, woqh, nullptr, nullptr };
        hgemm<0><<<dim3(DD / BN, (BB * LQ) / BM, 1), 256, SMEM_DYN>>>(
            s, 2, DD, out, nullptr, nullptr, DD, 0LL, 0LL, 0LL, 1.0f);
    }
}

// round 8
// speedup vs baseline: 7.9726x; 1.6404x over previous
#include <cuda_runtime.h>
#include <cuda_fp16.h>
#include <math.h>
#include <stdint.h>

#define BB 16
#define LQ 2048
#define LC 2048
#define DD 1024
#define NQ_ELEMS  (BB * LQ * DD)
#define NB_ELEMS  (BB * LC * DD)
#define NW_ELEMS  (DD * DD)
#define NA_ELEMS  ((long long)BB * LQ * LC)

// scratch (single fp16)
__device__ __half g_qh[NQ_ELEMS];
__device__ __half g_bh[NB_ELEMS];
__device__ __half g_bTh[NB_ELEMS];
__device__ __half g_ch[NB_ELEMS];
__device__ __half g_ah[NA_ELEMS];
__device__ __half g_vh[NQ_ELEMS];
__device__ __half g_wch[NW_ELEMS];
__device__ __half g_woqh[NW_ELEMS];
__device__ __half g_woch[NW_ELEMS];

// ---- helpers ----
__device__ __forceinline__ uint32_t smem_u32(const void* p) {
    uint32_t a;
    asm("{ .reg .u64 t; cvta.to.shared.u64 t, %1; cvt.u32.u64 %0, t; }" : "=r"(a) : "l"(p));
    return a;
}
__device__ __forceinline__ void cp16(uint32_t dst, const void* src) {
    asm volatile("cp.async.cg.shared.global [%0], [%1], 16;" :: "r"(dst), "l"(src) : "memory");
}
__device__ __forceinline__ void cp_commit() { asm volatile("cp.async.commit_group;" ::: "memory"); }
template <int N> __device__ __forceinline__ void cp_wait() {
    asm volatile("cp.async.wait_group %0;" :: "n"(N) : "memory");
}
__device__ __forceinline__ void ldm4(uint32_t* r, uint32_t addr) {
    asm volatile("ldmatrix.sync.aligned.m8n8.x4.shared.b16 {%0,%1,%2,%3}, [%4];"
                 : "=r"(r[0]), "=r"(r[1]), "=r"(r[2]), "=r"(r[3]) : "r"(addr));
}
__device__ __forceinline__ void mma16816(float* c, const uint32_t* a, const uint32_t* b) {
    asm volatile("mma.sync.aligned.m16n8k16.row.col.f32.f16.f16.f32 "
                 "{%0,%1,%2,%3},{%4,%5,%6,%7},{%8,%9},{%0,%1,%2,%3};"
                 : "+f"(c[0]), "+f"(c[1]), "+f"(c[2]), "+f"(c[3])
                 : "r"(a[0]), "r"(a[1]), "r"(a[2]), "r"(a[3]), "r"(b[0]), "r"(b[1]));
}

// ---- HMMA GEMM: C[M,N] = alpha * sum_seg A_s @ B_s^T ----
#define BM 128
#define BN 256
#define BK 64
#define STRD 72                    // BK + 8 pad (halfwords)
#define SA_BYTES (BM * STRD * 2)
#define SB_BYTES (BN * STRD * 2)
#define STAGE_BYTES (SA_BYTES + SB_BYTES)
#define NSTAGE 3
#define SMEM_DYN (NSTAGE * STAGE_BYTES)

struct GemmArgs {
    const __half *a0, *b0, *a1, *b1;
};

template <int MODE>  // 0: fp32 out; 2: fp16 out (Ch)
__global__ void __launch_bounds__(256)
hgemm(GemmArgs seg, int nseg, int K,
      float* __restrict__ Cf, __half* __restrict__ Ch,
      int ldc, long long sA, long long sB, long long sC, float alpha)
{
    extern __shared__ char dynsmem[];
    const uint32_t base0 = smem_u32(dynsmem);

    const int tid = threadIdx.x, lane = tid & 31, wid = tid >> 5;
    const int warp_m = wid & 1, warp_n = wid >> 1;   // 2x4 warps -> 64x64 per warp
    const int bm = blockIdx.y, bn = blockIdx.x, bz = blockIdx.z;

    const __half* Aseg[2] = { seg.a0, seg.a1 };
    const __half* Bseg[2] = { seg.b0, seg.b1 };

    const int tps = K / BK;
    const int CT = nseg * tps;

    float acc[4][8][4];
#pragma unroll
    for (int i = 0; i < 4; i++)
#pragma unroll
        for (int j = 0; j < 8; j++)
#pragma unroll
            for (int q = 0; q < 4; q++) acc[i][j][q] = 0.0f;

    const int lrow = tid >> 3, loff = (tid & 7) * 8;

    auto load_tile = [&](int t, int buf) {
        const int s = t / tps, kk = (t - s * tps) * BK;
        const __half* Ab = Aseg[s] + bz * sA + (long long)(bm * BM) * K + kk;
        const __half* Bb = Bseg[s] + bz * sB + (long long)(bn * BN) * K + kk;
        const uint32_t sa = base0 + buf * STAGE_BYTES;
        const uint32_t sb = sa + SA_BYTES;
#pragma unroll
        for (int i = 0; i < 4; i++) {
            const int row = lrow + i * 32;
            cp16(sa + (uint32_t)(row * STRD + loff) * 2, Ab + (long long)row * K + loff);
        }
#pragma unroll
        for (int i = 0; i < 8; i++) {
            const int row = lrow + i * 32;
            cp16(sb + (uint32_t)(row * STRD + loff) * 2, Bb + (long long)row * K + loff);
        }
        cp_commit();
    };

    const uint32_t a_base = (uint32_t)(((warp_m * 64 + (lane & 15)) * STRD + (lane >> 4) * 8) * 2);
    uint32_t b_base[4];
#pragma unroll
    for (int nf = 0; nf < 4; nf++)
        b_base[nf] = (uint32_t)(((warp_n * 64 + nf * 16 + ((lane >> 4) << 3) + (lane & 7)) * STRD
                                 + ((lane >> 3) & 1) * 8) * 2);

    uint32_t afr[2][4][4], bfr[2][8][2];
    auto ldfrag = [&](int buf, uint32_t sa, int kk) {
        const uint32_t sb = sa + SA_BYTES;
        const uint32_t kadd = (uint32_t)kk * 32;
#pragma unroll
        for (int im = 0; im < 4; im++)
            ldm4(afr[buf][im], sa + a_base + (uint32_t)(im * 16 * STRD * 2) + kadd);
#pragma unroll
        for (int nf = 0; nf < 4; nf++) {
            uint32_t r[4];
            ldm4(r, sb + b_base[nf] + kadd);
            bfr[buf][2 * nf][0] = r[0];     bfr[buf][2 * nf][1] = r[1];
            bfr[buf][2 * nf + 1][0] = r[2]; bfr[buf][2 * nf + 1][1] = r[3];
        }
    };

    load_tile(0, 0);
    if (CT > 1) load_tile(1, 1); else cp_commit();
    cp_wait<1>();
    __syncthreads();

    int cur = 0;
    ldfrag(0, base0, 0);

    for (int t = 0; t < CT; ++t) {
        const uint32_t sa_t = base0 + (t % NSTAGE) * STAGE_BYTES;
        if (t + 2 < CT) load_tile(t + 2, (t + 2) % NSTAGE); else cp_commit();

#pragma unroll
        for (int kk = 0; kk < 4; kk++) {
            if (kk < 3) ldfrag(cur ^ 1, sa_t, kk + 1);
#pragma unroll
            for (int im = 0; im < 4; im++)
#pragma unroll
                for (int in = 0; in < 8; in++)
                    mma16816(acc[im][in], afr[cur][im], bfr[cur][in]);
            cur ^= 1;
        }

        cp_wait<1>();
        __syncthreads();
        if (t + 1 < CT)
            ldfrag(cur, base0 + ((t + 1) % NSTAGE) * STAGE_BYTES, 0);
    }

    // epilogue
    const int gr = lane >> 2, qd = lane & 3;
#pragma unroll
    for (int im = 0; im < 4; im++) {
#pragma unroll
        for (int in = 0; in < 8; in++) {
            const long long row0 = (long long)bm * BM + warp_m * 64 + im * 16 + gr;
            const int col = bn * BN + warp_n * 64 + in * 8 + qd * 2;
#pragma unroll
            for (int h = 0; h < 2; h++) {
                const long long row = row0 + h * 8;
                const float v0 = alpha * acc[im][in][2 * h + 0];
                const float v1 = alpha * acc[im][in][2 * h + 1];
                if (MODE == 0) {
                    *(float2*)(Cf + bz * sC + row * ldc + col) = make_float2(v0, v1);
                } else {
                    *(__half2*)(Ch + bz * sC + row * ldc + col) =
                        __halves2half2(__float2half_rn(v0), __float2half_rn(v1));
                }
            }
        }
    }
}

// ---- fp32 -> fp16 convert ----
__global__ void __launch_bounds__(256)
conv_f16(const float4* __restrict__ src, __half2* __restrict__ dst, int n4)
{
    for (int i = blockIdx.x * blockDim.x + threadIdx.x; i < n4; i += gridDim.x * blockDim.x) {
        const float4 v = src[i];
        dst[2 * i]     = __halves2half2(__float2half_rn(v.x), __float2half_rn(v.y));
        dst[2 * i + 1] = __halves2half2(__float2half_rn(v.z), __float2half_rn(v.w));
    }
}

// ---- bank [b,K,D] fp32 -> bankT [b,D,K] fp16 ----
__global__ void __launch_bounds__(256)
transpose_h(const float* __restrict__ src, __half* __restrict__ dst)
{
    __shared__ float t[32][33];
    const int tx = threadIdx.x, ty = threadIdx.y;       // (32, 8)
    const int kb = blockIdx.y, db = blockIdx.x, b = blockIdx.z;
    const float* s = src + (long long)b * LC * DD;
#pragma unroll
    for (int r = 0; r < 4; r++)
        t[ty + r * 8][tx] = s[(long long)(kb * 32 + ty + r * 8) * DD + db * 32 + tx];
    __syncthreads();
    __half* o = dst + (long long)b * DD * LC;
#pragma unroll
    for (int r = 0; r < 4; r++) {
        const int drow = db * 32 + ty + r * 8;
        const int kcol = kb * 32 + tx;
        o[(long long)drow * LC + kcol] = __float2half_rn(t[tx][ty + r * 8]);
    }
}

// ---- softmax (fp32 in/out in place) + fp16 emit ----
__global__ void __launch_bounds__(256)
softmax_emit(float* __restrict__ data, __half* __restrict__ ah)
{
    const long long row = blockIdx.x;
    float* p = data + row * (long long)LC;
    const int tid = threadIdx.x;
    const int lane = tid & 31, wid = tid >> 5;
    __shared__ float sred[8];
    __shared__ float sbcast;

    float4 x0 = ((const float4*)p)[tid];
    float4 x1 = ((const float4*)p)[tid + 256];

    float m = fmaxf(fmaxf(fmaxf(x0.x, x0.y), fmaxf(x0.z, x0.w)),
                    fmaxf(fmaxf(x1.x, x1.y), fmaxf(x1.z, x1.w)));
#pragma unroll
    for (int off = 16; off; off >>= 1) m = fmaxf(m, __shfl_xor_sync(0xffffffffu, m, off));
    if (lane == 0) sred[wid] = m;
    __syncthreads();
    if (tid == 0) {
        float t = sred[0];
#pragma unroll
        for (int w = 1; w < 8; w++) t = fmaxf(t, sred[w]);
        sbcast = t;
    }
    __syncthreads();
    const float rowmax = sbcast;
    __syncthreads();

    float e[8];
    e[0] = expf(x0.x - rowmax); e[1] = expf(x0.y - rowmax);
    e[2] = expf(x0.z - rowmax); e[3] = expf(x0.w - rowmax);
    e[4] = expf(x1.x - rowmax); e[5] = expf(x1.y - rowmax);
    e[6] = expf(x1.z - rowmax); e[7] = expf(x1.w - rowmax);

    float ssum = 0.0f;
#pragma unroll
    for (int i = 0; i < 8; i++) ssum += e[i];
#pragma unroll
    for (int off = 16; off; off >>= 1) ssum += __shfl_xor_sync(0xffffffffu, ssum, off);
    if (lane == 0) sred[wid] = ssum;
    __syncthreads();
    if (tid == 0) {
        float t = 0.0f;
#pragma unroll
        for (int w = 0; w < 8; w++) t += sred[w];
        sbcast = t;
    }
    __syncthreads();
    const float inv = 1.0f / sbcast;

    float o[8];
#pragma unroll
    for (int i = 0; i < 8; i++) o[i] = e[i] * inv;

    ((float4*)p)[tid]       = make_float4(o[0], o[1], o[2], o[3]);
    ((float4*)p)[tid + 256] = make_float4(o[4], o[5], o[6], o[7]);

    __half2* oh = (__half2*)(ah + row * (long long)LC);
    oh[2 * tid]           = __halves2half2(__float2half_rn(o[0]), __float2half_rn(o[1]));
    oh[2 * tid + 1]       = __halves2half2(__float2half_rn(o[2]), __float2half_rn(o[3]));
    oh[512 + 2 * tid]     = __halves2half2(__float2half_rn(o[4]), __float2half_rn(o[5]));
    oh[512 + 2 * tid + 1] = __halves2half2(__float2half_rn(o[6]), __float2half_rn(o[7]));
}

static void* dsym(const void* sym) { void* p = nullptr; cudaGetSymbolAddress(&p, sym); return p; }

extern "C" void kernel_launch(void* const* d_in, const int* in_sizes, int n_in,
                              void* d_out, int out_size)
{
    const float* query = (const float*)d_in[0];
    const float* bank  = (const float*)d_in[1];
    const float* Wc    = (const float*)d_in[2];
    const float* Woq   = (const float*)d_in[3];
    const float* Woc   = (const float*)d_in[4];

    float* out  = (float*)d_out;
    float* attn = out + (long long)BB * LQ * DD;

    __half* qh  = (__half*)dsym(g_qh);
    __half* bh  = (__half*)dsym(g_bh);
    __half* bTh = (__half*)dsym(g_bTh);
    __half* ch  = (__half*)dsym(g_ch);
    __half* ah  = (__half*)dsym(g_ah);
    __half* vh  = (__half*)dsym(g_vh);
    __half* wch = (__half*)dsym(g_wch);
    __half* woqh= (__half*)dsym(g_woqh);
    __half* woch= (__half*)dsym(g_woch);

    cudaFuncSetAttribute(hgemm<0>, cudaFuncAttributeMaxDynamicSharedMemorySize, SMEM_DYN);
    cudaFuncSetAttribute(hgemm<2>, cudaFuncAttributeMaxDynamicSharedMemorySize, SMEM_DYN);

    conv_f16<<<4096, 256>>>((const float4*)query, (__half2*)qh, NQ_ELEMS / 4);
    conv_f16<<<4096, 256>>>((const float4*)bank,  (__half2*)bh, NB_ELEMS / 4);
    conv_f16<<<1024, 256>>>((const float4*)Wc,  (__half2*)wch,  NW_ELEMS / 4);
    conv_f16<<<1024, 256>>>((const float4*)Woq, (__half2*)woqh, NW_ELEMS / 4);
    conv_f16<<<1024, 256>>>((const float4*)Woc, (__half2*)woch, NW_ELEMS / 4);
    transpose_h<<<dim3(DD / 32, LC / 32, BB), dim3(32, 8)>>>(bank, bTh);

    // G1: ctx = bank @ Wc^T  (flat M=32768) -> fp16 ch
    {
        GemmArgs s = { bh, wch, nullptr, nullptr };
        hgemm<2><<<dim3(DD / BN, (BB * LC) / BM, 1), 256, SMEM_DYN>>>(
            s, 1, DD, nullptr, ch, DD, 0LL, 0LL, 0LL, 1.0f);
    }
    // G2: score = (1/32) q @ ctx^T  (per batch) -> attn fp32
    {
        GemmArgs s = { qh, ch, nullptr, nullptr };
        hgemm<0><<<dim3(LC / BN, LQ / BM, BB), 256, SMEM_DYN>>>(
            s, 1, DD, attn, nullptr, LC,
            (long long)LQ * DD, (long long)LC * DD, (long long)LQ * LC, 0.03125f);
    }
    softmax_emit<<<BB * LQ, 256>>>(attn, ah);

    // G3: context = attn @ bankT^T (per batch) -> fp16 vh
    {
        GemmArgs s = { ah, bTh, nullptr, nullptr };
        hgemm<2><<<dim3(DD / BN, LQ / BM, BB), 256, SMEM_DYN>>>(
            s, 1, LC, nullptr, vh, DD,
            (long long)LQ * LC, (long long)DD * LC, (long long)LQ * DD, 1.0f);
    }
    // G4: out = context @ Woc^T + q @ Woq^T (flat M=32768, 2 segs) -> fp32
    {
        GemmArgs s = { vh, woch, qh, woqh };
        hgemm<0><<<dim3(DD / BN, (BB * LQ) / BM, 1), 256, SMEM_DYN>>>(
            s, 2, DD, out, nullptr, DD, 0LL, 0LL, 0LL, 1.0f);
    }
}

// round 9
// speedup vs baseline: 8.0625x; 1.0113x over previous
#include <cuda_runtime.h>
#include <cuda_fp16.h>
#include <math.h>
#include <stdint.h>

#define BB 16
#define LQ 2048
#define LC 2048
#define DD 1024
#define NQ_ELEMS  (BB * LQ * DD)
#define NB_ELEMS  (BB * LC * DD)
#define NW_ELEMS  (DD * DD)
#define NA_ELEMS  ((long long)BB * LQ * LC)

// scratch (single fp16)
__device__ __half g_qh[NQ_ELEMS];
__device__ __half g_bh[NB_ELEMS];
__device__ __half g_ch[NB_ELEMS];
__device__ __half g_ah[NA_ELEMS];
__device__ __half g_vh[NQ_ELEMS];
__device__ __half g_wch[NW_ELEMS];
__device__ __half g_woqh[NW_ELEMS];
__device__ __half g_woch[NW_ELEMS];

// ---- helpers ----
__device__ __forceinline__ uint32_t smem_u32(const void* p) {
    uint32_t a;
    asm("{ .reg .u64 t; cvta.to.shared.u64 t, %1; cvt.u32.u64 %0, t; }" : "=r"(a) : "l"(p));
    return a;
}
__device__ __forceinline__ void cp16(uint32_t dst, const void* src) {
    asm volatile("cp.async.cg.shared.global [%0], [%1], 16;" :: "r"(dst), "l"(src) : "memory");
}
__device__ __forceinline__ void cp_commit() { asm volatile("cp.async.commit_group;" ::: "memory"); }
template <int N> __device__ __forceinline__ void cp_wait() {
    asm volatile("cp.async.wait_group %0;" :: "n"(N) : "memory");
}
__device__ __forceinline__ void ldm4(uint32_t* r, uint32_t addr) {
    asm volatile("ldmatrix.sync.aligned.m8n8.x4.shared.b16 {%0,%1,%2,%3}, [%4];"
                 : "=r"(r[0]), "=r"(r[1]), "=r"(r[2]), "=r"(r[3]) : "r"(addr));
}
__device__ __forceinline__ void ldm4t(uint32_t* r, uint32_t addr) {
    asm volatile("ldmatrix.sync.aligned.m8n8.x4.trans.shared.b16 {%0,%1,%2,%3}, [%4];"
                 : "=r"(r[0]), "=r"(r[1]), "=r"(r[2]), "=r"(r[3]) : "r"(addr));
}
__device__ __forceinline__ void mma16816(float* c, const uint32_t* a, const uint32_t* b) {
    asm volatile("mma.sync.aligned.m16n8k16.row.col.f32.f16.f16.f32 "
                 "{%0,%1,%2,%3},{%4,%5,%6,%7},{%8,%9},{%0,%1,%2,%3};"
                 : "+f"(c[0]), "+f"(c[1]), "+f"(c[2]), "+f"(c[3])
                 : "r"(a[0]), "r"(a[1]), "r"(a[2]), "r"(a[3]), "r"(b[0]), "r"(b[1]));
}

// ---- HMMA GEMM ----
// BNN=0: C = alpha * sum_seg A_s @ B_s^T   (B_s: [N,K] row-major, ld=ldB)
// BNN=1: C = alpha * A @ B                  (B: [K,N] row-major, ld=ldB)
#define BM 128
#define BN 256
#define BK 64
#define STRD 72                     // NT: BK + 8 pad (halfwords)
#define STRDN 264                   // NN: BN + 8 pad (halfwords)
#define SA_BYTES (BM * STRD * 2)
#define SB_BYTES (BN * STRD * 2)    // >= 64*STRDN*2 = 33792, ok
#define STAGE_BYTES (SA_BYTES + SB_BYTES)
#define NSTAGE 3
#define SMEM_DYN (NSTAGE * STAGE_BYTES)

struct GemmArgs {
    const __half *a0, *b0, *a1, *b1;
};

template <int MODE, int BNN>  // MODE 0: fp32 out; 2: fp16 out
__global__ void __launch_bounds__(256)
hgemm(GemmArgs seg, int nseg, int K, int ldB,
      float* __restrict__ Cf, __half* __restrict__ Ch,
      int ldc, long long sA, long long sB, long long sC, float alpha)
{
    extern __shared__ char dynsmem[];
    const uint32_t base0 = smem_u32(dynsmem);

    const int tid = threadIdx.x, lane = tid & 31, wid = tid >> 5;
    const int warp_m = wid & 1, warp_n = wid >> 1;   // 2x4 warps -> 64x64 per warp
    const int bm = blockIdx.y, bn = blockIdx.x, bz = blockIdx.z;

    const __half* Aseg[2] = { seg.a0, seg.a1 };
    const __half* Bseg[2] = { seg.b0, seg.b1 };

    const int tps = K / BK;
    const int CT = nseg * tps;

    float acc[4][8][4];
#pragma unroll
    for (int i = 0; i < 4; i++)
#pragma unroll
        for (int j = 0; j < 8; j++)
#pragma unroll
            for (int q = 0; q < 4; q++) acc[i][j][q] = 0.0f;

    const int lrow = tid >> 3, loff = (tid & 7) * 8;      // NT loader / A loader
    const int nrow = tid >> 5, noff = (tid & 31) * 8;     // NN B loader (64 rows x 256 hw)

    auto load_tile = [&](int t, int buf) {
        const int s = t / tps, kk = (t - s * tps) * BK;
        const __half* Ab = Aseg[s] + bz * sA + (long long)(bm * BM) * K + kk;
        const uint32_t sa = base0 + buf * STAGE_BYTES;
        const uint32_t sb = sa + SA_BYTES;
#pragma unroll
        for (int i = 0; i < 4; i++) {
            const int row = lrow + i * 32;
            cp16(sa + (uint32_t)(row * STRD + loff) * 2, Ab + (long long)row * K + loff);
        }
        if (BNN == 0) {
            const __half* Bb = Bseg[s] + bz * sB + (long long)(bn * BN) * ldB + kk;
#pragma unroll
            for (int i = 0; i < 8; i++) {
                const int row = lrow + i * 32;
                cp16(sb + (uint32_t)(row * STRD + loff) * 2, Bb + (long long)row * ldB + loff);
            }
        } else {
            const __half* Bb = Bseg[s] + bz * sB + (long long)kk * ldB + bn * BN;
#pragma unroll
            for (int i = 0; i < 8; i++) {
                const int row = nrow + i * 8;
                cp16(sb + (uint32_t)(row * STRDN + noff) * 2, Bb + (long long)row * ldB + noff);
            }
        }
        cp_commit();
    };

    // ldmatrix per-thread byte offsets
    const uint32_t a_base = (uint32_t)(((warp_m * 64 + (lane & 15)) * STRD + (lane >> 4) * 8) * 2);
    uint32_t b_base[4];
#pragma unroll
    for (int nf = 0; nf < 4; nf++) {
        if (BNN == 0)
            b_base[nf] = (uint32_t)(((warp_n * 64 + nf * 16 + ((lane >> 4) << 3) + (lane & 7)) * STRD
                                     + ((lane >> 3) & 1) * 8) * 2);
        else
            b_base[nf] = (uint32_t)(((lane & 15) * STRDN
                                     + warp_n * 64 + nf * 16 + (lane >> 4) * 8) * 2);
    }

    uint32_t afr[2][4][4], bfr[2][8][2];
    auto ldfrag = [&](int buf, uint32_t sa, int kk) {
        const uint32_t sb = sa + SA_BYTES;
        const uint32_t kaddA = (uint32_t)kk * 32;
#pragma unroll
        for (int im = 0; im < 4; im++)
            ldm4(afr[buf][im], sa + a_base + (uint32_t)(im * 16 * STRD * 2) + kaddA);
        const uint32_t kaddB = (BNN == 0) ? (uint32_t)kk * 32 : (uint32_t)kk * 16 * STRDN * 2;
#pragma unroll
        for (int nf = 0; nf < 4; nf++) {
            uint32_t r[4];
            if (BNN == 0) ldm4(r, sb + b_base[nf] + kaddB);
            else          ldm4t(r, sb + b_base[nf] + kaddB);
            bfr[buf][2 * nf][0] = r[0];     bfr[buf][2 * nf][1] = r[1];
            bfr[buf][2 * nf + 1][0] = r[2]; bfr[buf][2 * nf + 1][1] = r[3];
        }
    };

    load_tile(0, 0);
    if (CT > 1) load_tile(1, 1); else cp_commit();
    cp_wait<1>();
    __syncthreads();

    int cur = 0;
    ldfrag(0, base0, 0);

    for (int t = 0; t < CT; ++t) {
        const uint32_t sa_t = base0 + (t % NSTAGE) * STAGE_BYTES;
        if (t + 2 < CT) load_tile(t + 2, (t + 2) % NSTAGE); else cp_commit();

#pragma unroll
        for (int kk = 0; kk < 4; kk++) {
            if (kk < 3) ldfrag(cur ^ 1, sa_t, kk + 1);
#pragma unroll
            for (int im = 0; im < 4; im++)
#pragma unroll
                for (int in = 0; in < 8; in++)
                    mma16816(acc[im][in], afr[cur][im], bfr[cur][in]);
            cur ^= 1;
        }

        cp_wait<1>();
        __syncthreads();
        if (t + 1 < CT)
            ldfrag(cur, base0 + ((t + 1) % NSTAGE) * STAGE_BYTES, 0);
    }

    // epilogue
    const int gr = lane >> 2, qd = lane & 3;
#pragma unroll
    for (int im = 0; im < 4; im++) {
#pragma unroll
        for (int in = 0; in < 8; in++) {
            const long long row0 = (long long)bm * BM + warp_m * 64 + im * 16 + gr;
            const int col = bn * BN + warp_n * 64 + in * 8 + qd * 2;
#pragma unroll
            for (int h = 0; h < 2; h++) {
                const long long row = row0 + h * 8;
                const float v0 = alpha * acc[im][in][2 * h + 0];
                const float v1 = alpha * acc[im][in][2 * h + 1];
                if (MODE == 0) {
                    *(float2*)(Cf + bz * sC + row * ldc + col) = make_float2(v0, v1);
                } else {
                    *(__half2*)(Ch + bz * sC + row * ldc + col) =
                        __halves2half2(__float2half_rn(v0), __float2half_rn(v1));
                }
            }
        }
    }
}

// ---- fp32 -> fp16 convert ----
__global__ void __launch_bounds__(256)
conv_f16(const float4* __restrict__ src, __half2* __restrict__ dst, int n4)
{
    for (int i = blockIdx.x * blockDim.x + threadIdx.x; i < n4; i += gridDim.x * blockDim.x) {
        const float4 v = src[i];
        dst[2 * i]     = __halves2half2(__float2half_rn(v.x), __float2half_rn(v.y));
        dst[2 * i + 1] = __halves2half2(__float2half_rn(v.z), __float2half_rn(v.w));
    }
}

// ---- softmax: fp16 score in (in-place normalize) + fp32 attn out ----
__global__ void __launch_bounds__(256)
softmax_h(__half* __restrict__ score, float* __restrict__ attn)
{
    const long long row = blockIdx.x;
    __half* ps = score + row * (long long)LC;
    float* pa = attn + row * (long long)LC;
    const int tid = threadIdx.x;
    const int lane = tid & 31, wid = tid >> 5;
    __shared__ float sred[8];
    __shared__ float sbcast;

    const uint4 v = ((const uint4*)ps)[tid];   // 8 halfs
    float f[8];
    {
        const __half2* hp = (const __half2*)&v;
#pragma unroll
        for (int i = 0; i < 4; i++) {
            const float2 t = __half22float2(hp[i]);
            f[2 * i] = t.x; f[2 * i + 1] = t.y;
        }
    }

    float m = f[0];
#pragma unroll
    for (int i = 1; i < 8; i++) m = fmaxf(m, f[i]);
#pragma unroll
    for (int off = 16; off; off >>= 1) m = fmaxf(m, __shfl_xor_sync(0xffffffffu, m, off));
    if (lane == 0) sred[wid] = m;
    __syncthreads();
    if (tid == 0) {
        float t = sred[0];
#pragma unroll
        for (int w = 1; w < 8; w++) t = fmaxf(t, sred[w]);
        sbcast = t;
    }
    __syncthreads();
    const float rowmax = sbcast;
    __syncthreads();

    float e[8], ssum = 0.0f;
#pragma unroll
    for (int i = 0; i < 8; i++) { e[i] = expf(f[i] - rowmax); ssum += e[i]; }
#pragma unroll
    for (int off = 16; off; off >>= 1) ssum += __shfl_xor_sync(0xffffffffu, ssum, off);
    if (lane == 0) sred[wid] = ssum;
    __syncthreads();
    if (tid == 0) {
        float t = 0.0f;
#pragma unroll
        for (int w = 0; w < 8; w++) t += sred[w];
        sbcast = t;
    }
    __syncthreads();
    const float inv = 1.0f / sbcast;

    float o[8];
#pragma unroll
    for (int i = 0; i < 8; i++) o[i] = e[i] * inv;

    ((float4*)pa)[2 * tid]     = make_float4(o[0], o[1], o[2], o[3]);
    ((float4*)pa)[2 * tid + 1] = make_float4(o[4], o[5], o[6], o[7]);

    uint4 w;
    __half2* wp = (__half2*)&w;
#pragma unroll
    for (int i = 0; i < 4; i++)
        wp[i] = __halves2half2(__float2half_rn(o[2 * i]), __float2half_rn(o[2 * i + 1]));
    ((uint4*)ps)[tid] = w;
}

static void* dsym(const void* sym) { void* p = nullptr; cudaGetSymbolAddress(&p, sym); return p; }

extern "C" void kernel_launch(void* const* d_in, const int* in_sizes, int n_in,
                              void* d_out, int out_size)
{
    const float* query = (const float*)d_in[0];
    const float* bank  = (const float*)d_in[1];
    const float* Wc    = (const float*)d_in[2];
    const float* Woq   = (const float*)d_in[3];
    const float* Woc   = (const float*)d_in[4];

    float* out  = (float*)d_out;
    float* attn = out + (long long)BB * LQ * DD;

    __half* qh  = (__half*)dsym(g_qh);
    __half* bh  = (__half*)dsym(g_bh);
    __half* ch  = (__half*)dsym(g_ch);
    __half* ah  = (__half*)dsym(g_ah);
    __half* vh  = (__half*)dsym(g_vh);
    __half* wch = (__half*)dsym(g_wch);
    __half* woqh= (__half*)dsym(g_woqh);
    __half* woch= (__half*)dsym(g_woch);

    cudaFuncSetAttribute(hgemm<0,0>, cudaFuncAttributeMaxDynamicSharedMemorySize, SMEM_DYN);
    cudaFuncSetAttribute(hgemm<2,0>, cudaFuncAttributeMaxDynamicSharedMemorySize, SMEM_DYN);
    cudaFuncSetAttribute(hgemm<2,1>, cudaFuncAttributeMaxDynamicSharedMemorySize, SMEM_DYN);

    conv_f16<<<4096, 256>>>((const float4*)query, (__half2*)qh, NQ_ELEMS / 4);
    conv_f16<<<4096, 256>>>((const float4*)bank,  (__half2*)bh, NB_ELEMS / 4);
    conv_f16<<<1024, 256>>>((const float4*)Wc,  (__half2*)wch,  NW_ELEMS / 4);
    conv_f16<<<1024, 256>>>((const float4*)Woq, (__half2*)woqh, NW_ELEMS / 4);
    conv_f16<<<1024, 256>>>((const float4*)Woc, (__half2*)woch, NW_ELEMS / 4);

    // G1: ctx = bank @ Wc^T (flat M=32768) -> fp16 ch
    {
        GemmArgs s = { bh, wch, nullptr, nullptr };
        hgemm<2,0><<<dim3(DD / BN, (BB * LC) / BM, 1), 256, SMEM_DYN>>>(
            s, 1, DD, DD, nullptr, ch, DD, 0LL, 0LL, 0LL, 1.0f);
    }
    // G2: score = (1/32) q @ ctx^T (per batch) -> fp16 score in ah
    {
        GemmArgs s = { qh, ch, nullptr, nullptr };
        hgemm<2,0><<<dim3(LC / BN, LQ / BM, BB), 256, SMEM_DYN>>>(
            s, 1, DD, DD, nullptr, ah, LC,
            (long long)LQ * DD, (long long)LC * DD, (long long)LQ * LC, 0.03125f);
    }
    // softmax: ah (score fp16) -> attn fp32 (d_out) + ah normalized fp16 in place
    softmax_h<<<BB * LQ, 256>>>(ah, attn);

    // G3: context = attn @ bank (NN, per batch) -> fp16 vh
    {
        GemmArgs s = { ah, bh, nullptr, nullptr };
        hgemm<2,1><<<dim3(DD / BN, LQ / BM, BB), 256, SMEM_DYN>>>(
            s, 1, LC, DD, nullptr, vh, DD,
            (long long)LQ * LC, (long long)LC * DD, (long long)LQ * DD, 1.0f);
    }
    // G4: out = context @ Woc^T + q @ Woq^T (flat M=32768, 2 segs) -> fp32
    {
        GemmArgs s = { vh, woch, qh, woqh };
        hgemm<0,0><<<dim3(DD / BN, (BB * LQ) / BM, 1), 256, SMEM_DYN>>>(
            s, 2, DD, DD, out, nullptr, DD, 0LL, 0LL, 0LL, 1.0f);
    }
}

// round 10
// speedup vs baseline: 8.1000x; 1.0046x over previous
#include <cuda_runtime.h>
#include <cuda_fp16.h>
#include <math.h>
#include <stdint.h>

#define BB 16
#define LQ 2048
#define LC 2048
#define DD 1024
#define NQ_ELEMS  (BB * LQ * DD)
#define NB_ELEMS  (BB * LC * DD)
#define NW_ELEMS  (DD * DD)
#define NA_ELEMS  ((long long)BB * LQ * LC)

// scratch (single fp16)
__device__ __half g_qh[NQ_ELEMS];
__device__ __half g_bh[NB_ELEMS];
__device__ __half g_qwh[NQ_ELEMS];
__device__ __half g_eh[NA_ELEMS];
__device__ __half g_vh[NQ_ELEMS];
__device__ __half g_wch[NW_ELEMS];
__device__ __half g_woqh[NW_ELEMS];
__device__ __half g_woch[NW_ELEMS];
__device__ float  g_rowinv[BB * LQ];

// ---- helpers ----
__device__ __forceinline__ uint32_t smem_u32(const void* p) {
    uint32_t a;
    asm("{ .reg .u64 t; cvta.to.shared.u64 t, %1; cvt.u32.u64 %0, t; }" : "=r"(a) : "l"(p));
    return a;
}
__device__ __forceinline__ void cp16(uint32_t dst, const void* src) {
    asm volatile("cp.async.cg.shared.global [%0], [%1], 16;" :: "r"(dst), "l"(src) : "memory");
}
__device__ __forceinline__ void cp_commit() { asm volatile("cp.async.commit_group;" ::: "memory"); }
template <int N> __device__ __forceinline__ void cp_wait() {
    asm volatile("cp.async.wait_group %0;" :: "n"(N) : "memory");
}
__device__ __forceinline__ void ldm4(uint32_t* r, uint32_t addr) {
    asm volatile("ldmatrix.sync.aligned.m8n8.x4.shared.b16 {%0,%1,%2,%3}, [%4];"
                 : "=r"(r[0]), "=r"(r[1]), "=r"(r[2]), "=r"(r[3]) : "r"(addr));
}
__device__ __forceinline__ void ldm4t(uint32_t* r, uint32_t addr) {
    asm volatile("ldmatrix.sync.aligned.m8n8.x4.trans.shared.b16 {%0,%1,%2,%3}, [%4];"
                 : "=r"(r[0]), "=r"(r[1]), "=r"(r[2]), "=r"(r[3]) : "r"(addr));
}
__device__ __forceinline__ void mma16816(float* c, const uint32_t* a, const uint32_t* b) {
    asm volatile("mma.sync.aligned.m16n8k16.row.col.f32.f16.f16.f32 "
                 "{%0,%1,%2,%3},{%4,%5,%6,%7},{%8,%9},{%0,%1,%2,%3};"
                 : "+f"(c[0]), "+f"(c[1]), "+f"(c[2]), "+f"(c[3])
                 : "r"(a[0]), "r"(a[1]), "r"(a[2]), "r"(a[3]), "r"(b[0]), "r"(b[1]));
}

// ---- HMMA GEMM ----
// BNN=0: C = alpha * sum_seg A_s @ B_s^T   (B_s: [N,K] row-major, ld=ldB)
// BNN=1: C = alpha * A @ B                  (B: [K,N] row-major, ld=ldB)
// MODE 0: fp32 out; 2: fp16 out; 3: fp16 exp(alpha*v) out; 4: fp16 (v*rowscale) out
#define BM 128
#define BN 256
#define BK 64
#define STRD 72
#define STRDN 264
#define SA_BYTES (BM * STRD * 2)
#define SB_BYTES (BN * STRD * 2)
#define STAGE_BYTES (SA_BYTES + SB_BYTES)
#define NSTAGE 3
#define SMEM_DYN (NSTAGE * STAGE_BYTES)

struct GemmArgs {
    const __half *a0, *b0, *a1, *b1;
};

template <int MODE, int BNN>
__global__ void __launch_bounds__(256)
hgemm(GemmArgs seg, int nseg, int K, int ldB,
      float* __restrict__ Cf, __half* __restrict__ Ch,
      const float* __restrict__ rowscale, int rsbase,
      int ldc, long long sA, long long sB, long long sC, float alpha)
{
    extern __shared__ char dynsmem[];
    const uint32_t base0 = smem_u32(dynsmem);

    const int tid = threadIdx.x, lane = tid & 31, wid = tid >> 5;
    const int warp_m = wid & 1, warp_n = wid >> 1;   // 2x4 warps -> 64x64 per warp
    const int bm = blockIdx.y, bn = blockIdx.x, bz = blockIdx.z;

    const __half* Aseg[2] = { seg.a0, seg.a1 };
    const __half* Bseg[2] = { seg.b0, seg.b1 };

    const int tps = K / BK;
    const int CT = nseg * tps;

    float acc[4][8][4];
#pragma unroll
    for (int i = 0; i < 4; i++)
#pragma unroll
        for (int j = 0; j < 8; j++)
#pragma unroll
            for (int q = 0; q < 4; q++) acc[i][j][q] = 0.0f;

    const int lrow = tid >> 3, loff = (tid & 7) * 8;
    const int nrow = tid >> 5, noff = (tid & 31) * 8;

    auto load_tile = [&](int t, int buf) {
        const int s = t / tps, kk = (t - s * tps) * BK;
        const __half* Ab = Aseg[s] + bz * sA + (long long)(bm * BM) * K + kk;
        const uint32_t sa = base0 + buf * STAGE_BYTES;
        const uint32_t sb = sa + SA_BYTES;
#pragma unroll
        for (int i = 0; i < 4; i++) {
            const int row = lrow + i * 32;
            cp16(sa + (uint32_t)(row * STRD + loff) * 2, Ab + (long long)row * K + loff);
        }
        if (BNN == 0) {
            const __half* Bb = Bseg[s] + bz * sB + (long long)(bn * BN) * ldB + kk;
#pragma unroll
            for (int i = 0; i < 8; i++) {
                const int row = lrow + i * 32;
                cp16(sb + (uint32_t)(row * STRD + loff) * 2, Bb + (long long)row * ldB + loff);
            }
        } else {
            const __half* Bb = Bseg[s] + bz * sB + (long long)kk * ldB + bn * BN;
#pragma unroll
            for (int i = 0; i < 8; i++) {
                const int row = nrow + i * 8;
                cp16(sb + (uint32_t)(row * STRDN + noff) * 2, Bb + (long long)row * ldB + noff);
            }
        }
        cp_commit();
    };

    const uint32_t a_base = (uint32_t)(((warp_m * 64 + (lane & 15)) * STRD + (lane >> 4) * 8) * 2);
    uint32_t b_base[4];
#pragma unroll
    for (int nf = 0; nf < 4; nf++) {
        if (BNN == 0)
            b_base[nf] = (uint32_t)(((warp_n * 64 + nf * 16 + ((lane >> 4) << 3) + (lane & 7)) * STRD
                                     + ((lane >> 3) & 1) * 8) * 2);
        else
            b_base[nf] = (uint32_t)(((lane & 15) * STRDN
                                     + warp_n * 64 + nf * 16 + (lane >> 4) * 8) * 2);
    }

    uint32_t afr[2][4][4], bfr[2][8][2];
    auto ldfrag = [&](int buf, uint32_t sa, int kk) {
        const uint32_t sb = sa + SA_BYTES;
        const uint32_t kaddA = (uint32_t)kk * 32;
#pragma unroll
        for (int im = 0; im < 4; im++)
            ldm4(afr[buf][im], sa + a_base + (uint32_t)(im * 16 * STRD * 2) + kaddA);
        const uint32_t kaddB = (BNN == 0) ? (uint32_t)kk * 32 : (uint32_t)kk * 16 * STRDN * 2;
#pragma unroll
        for (int nf = 0; nf < 4; nf++) {
            uint32_t r[4];
            if (BNN == 0) ldm4(r, sb + b_base[nf] + kaddB);
            else          ldm4t(r, sb + b_base[nf] + kaddB);
            bfr[buf][2 * nf][0] = r[0];     bfr[buf][2 * nf][1] = r[1];
            bfr[buf][2 * nf + 1][0] = r[2]; bfr[buf][2 * nf + 1][1] = r[3];
        }
    };

    load_tile(0, 0);
    if (CT > 1) load_tile(1, 1); else cp_commit();
    cp_wait<1>();
    __syncthreads();

    int cur = 0;
    ldfrag(0, base0, 0);

    for (int t = 0; t < CT; ++t) {
        const uint32_t sa_t = base0 + (t % NSTAGE) * STAGE_BYTES;
        if (t + 2 < CT) load_tile(t + 2, (t + 2) % NSTAGE); else cp_commit();

#pragma unroll
        for (int kk = 0; kk < 4; kk++) {
            if (kk < 3) ldfrag(cur ^ 1, sa_t, kk + 1);
#pragma unroll
            for (int im = 0; im < 4; im++)
#pragma unroll
                for (int in = 0; in < 8; in++)
                    mma16816(acc[im][in], afr[cur][im], bfr[cur][in]);
            cur ^= 1;
        }

        cp_wait<1>();
        __syncthreads();
        if (t + 1 < CT)
            ldfrag(cur, base0 + ((t + 1) % NSTAGE) * STAGE_BYTES, 0);
    }

    // epilogue
    const int gr = lane >> 2, qd = lane & 3;
    float rs[4][2];
    if (MODE == 4) {
#pragma unroll
        for (int im = 0; im < 4; im++)
#pragma unroll
            for (int h = 0; h < 2; h++)
                rs[im][h] = rowscale[rsbase + bz * LQ + bm * BM + warp_m * 64 + im * 16 + gr + h * 8];
    }
#pragma unroll
    for (int im = 0; im < 4; im++) {
#pragma unroll
        for (int in = 0; in < 8; in++) {
            const long long row0 = (long long)bm * BM + warp_m * 64 + im * 16 + gr;
            const int col = bn * BN + warp_n * 64 + in * 8 + qd * 2;
#pragma unroll
            for (int h = 0; h < 2; h++) {
                const long long row = row0 + h * 8;
                float v0 = acc[im][in][2 * h + 0];
                float v1 = acc[im][in][2 * h + 1];
                if (MODE == 0) {
                    *(float2*)(Cf + bz * sC + row * ldc + col) = make_float2(alpha * v0, alpha * v1);
                } else if (MODE == 2) {
                    *(__half2*)(Ch + bz * sC + row * ldc + col) =
                        __halves2half2(__float2half_rn(alpha * v0), __float2half_rn(alpha * v1));
                } else if (MODE == 3) {
                    *(__half2*)(Ch + bz * sC + row * ldc + col) =
                        __halves2half2(__float2half_rn(expf(alpha * v0)),
                                       __float2half_rn(expf(alpha * v1)));
                } else {  // MODE 4
                    const float s = rs[im][h];
                    *(__half2*)(Ch + bz * sC + row * ldc + col) =
                        __halves2half2(__float2half_rn(s * v0), __float2half_rn(s * v1));
                }
            }
        }
    }
}

// ---- fp32 -> fp16 convert (two arrays in one launch) ----
__global__ void __launch_bounds__(256)
conv2_f16(const float4* __restrict__ s0, __half2* __restrict__ d0, int n0,
          const float4* __restrict__ s1, __half2* __restrict__ d1, int n1)
{
    const int total = n0 + n1;
    for (int i = blockIdx.x * blockDim.x + threadIdx.x; i < total; i += gridDim.x * blockDim.x) {
        const float4* s = (i < n0) ? s0 : s1;
        __half2* d = (i < n0) ? d0 : d1;
        const int j = (i < n0) ? i : i - n0;
        const float4 v = s[j];
        d[2 * j]     = __halves2half2(__float2half_rn(v.x), __float2half_rn(v.y));
        d[2 * j + 1] = __halves2half2(__float2half_rn(v.z), __float2half_rn(v.w));
    }
}

// ---- three weight matrices in one launch ----
__global__ void __launch_bounds__(256)
conv3_f16(const float4* __restrict__ s0, __half2* __restrict__ d0,
          const float4* __restrict__ s1, __half2* __restrict__ d1,
          const float4* __restrict__ s2, __half2* __restrict__ d2, int n)
{
    for (int i = blockIdx.x * blockDim.x + threadIdx.x; i < 3 * n; i += gridDim.x * blockDim.x) {
        const int sel = i / n, j = i - sel * n;
        const float4* s = (sel == 0) ? s0 : (sel == 1) ? s1 : s2;
        __half2* d = (sel == 0) ? d0 : (sel == 1) ? d1 : d2;
        const float4 v = s[j];
        d[2 * j]     = __halves2half2(__float2half_rn(v.x), __float2half_rn(v.y));
        d[2 * j + 1] = __halves2half2(__float2half_rn(v.z), __float2half_rn(v.w));
    }
}

// ---- sum rows of E (fp16), emit attn fp32 = E*inv and rowinv ----
__global__ void __launch_bounds__(256)
sumscale(const __half* __restrict__ E, float* __restrict__ attn, float* __restrict__ rowinv)
{
    const long long row = blockIdx.x;
    const __half* pe = E + row * (long long)LC;
    float* pa = attn + row * (long long)LC;
    const int tid = threadIdx.x;
    const int lane = tid & 31, wid = tid >> 5;
    __shared__ float sred[8];
    __shared__ float sbcast;

    const uint4 v = ((const uint4*)pe)[tid];   // 8 halfs
    float f[8];
    {
        const __half2* hp = (const __half2*)&v;
#pragma unroll
        for (int i = 0; i < 4; i++) {
            const float2 t = __half22float2(hp[i]);
            f[2 * i] = t.x; f[2 * i + 1] = t.y;
        }
    }

    float ssum = 0.0f;
#pragma unroll
    for (int i = 0; i < 8; i++) ssum += f[i];
#pragma unroll
    for (int off = 16; off; off >>= 1) ssum += __shfl_xor_sync(0xffffffffu, ssum, off);
    if (lane == 0) sred[wid] = ssum;
    __syncthreads();
    if (tid == 0) {
        float t = 0.0f;
#pragma unroll
        for (int w = 0; w < 8; w++) t += sred[w];
        sbcast = 1.0f / t;
        rowinv[row] = sbcast;
    }
    __syncthreads();
    const float inv = sbcast;

    ((float4*)pa)[2 * tid]     = make_float4(f[0] * inv, f[1] * inv, f[2] * inv, f[3] * inv);
    ((float4*)pa)[2 * tid + 1] = make_float4(f[4] * inv, f[5] * inv, f[6] * inv, f[7] * inv);
}

static void* dsym(const void* sym) { void* p = nullptr; cudaGetSymbolAddress(&p, sym); return p; }

extern "C" void kernel_launch(void* const* d_in, const int* in_sizes, int n_in,
                              void* d_out, int out_size)
{
    const float* query = (const float*)d_in[0];
    const float* bank  = (const float*)d_in[1];
    const float* Wc    = (const float*)d_in[2];
    const float* Woq   = (const float*)d_in[3];
    const float* Woc   = (const float*)d_in[4];

    float* out  = (float*)d_out;
    float* attn = out + (long long)BB * LQ * DD;

    __half* qh   = (__half*)dsym(g_qh);
    __half* bh   = (__half*)dsym(g_bh);
    __half* qwh  = (__half*)dsym(g_qwh);
    __half* eh   = (__half*)dsym(g_eh);
    __half* vh   = (__half*)dsym(g_vh);
    __half* wch  = (__half*)dsym(g_wch);
    __half* woqh = (__half*)dsym(g_woqh);
    __half* woch = (__half*)dsym(g_woch);
    float*  rinv = (float*)dsym(g_rowinv);

    cudaFuncSetAttribute(hgemm<0,0>, cudaFuncAttributeMaxDynamicSharedMemorySize, SMEM_DYN);
    cudaFuncSetAttribute(hgemm<2,1>, cudaFuncAttributeMaxDynamicSharedMemorySize, SMEM_DYN);
    cudaFuncSetAttribute(hgemm<3,0>, cudaFuncAttributeMaxDynamicSharedMemorySize, SMEM_DYN);
    cudaFuncSetAttribute(hgemm<4,1>, cudaFuncAttributeMaxDynamicSharedMemorySize, SMEM_DYN);

    conv2_f16<<<8192, 256>>>((const float4*)query, (__half2*)qh, NQ_ELEMS / 4,
                             (const float4*)bank,  (__half2*)bh, NB_ELEMS / 4);
    conv3_f16<<<1536, 256>>>((const float4*)Wc,  (__half2*)wch,
                             (const float4*)Woq, (__half2*)woqh,
                             (const float4*)Woc, (__half2*)woch, NW_ELEMS / 4);

    // G1': qW = q @ Wc (NN, flat M=32768) -> fp16 qwh
    {
        GemmArgs s = { qh, wch, nullptr, nullptr };
        hgemm<2,1><<<dim3(DD / BN, (BB * LQ) / BM, 1), 256, SMEM_DYN>>>(
            s, 1, DD, DD, nullptr, qwh, nullptr, 0, DD, 0LL, 0LL, 0LL, 1.0f);
    }
    // G2': E = exp((1/32) qW @ bank^T) (NT, per batch) -> fp16 eh
    {
        GemmArgs s = { qwh, bh, nullptr, nullptr };
        hgemm<3,0><<<dim3(LC / BN, LQ / BM, BB), 256, SMEM_DYN>>>(
            s, 1, DD, DD, nullptr, eh, nullptr, 0, LC,
            (long long)LQ * DD, (long long)LC * DD, (long long)LQ * LC, 0.03125f);
    }
    // sums + attn fp32 output + rowinv
    sumscale<<<BB * LQ, 256>>>(eh, attn, rinv);

    // G3: context = (E @ bank) * rowinv (NN, per batch) -> fp16 vh
    {
        GemmArgs s = { eh, bh, nullptr, nullptr };
        hgemm<4,1><<<dim3(DD / BN, LQ / BM, BB), 256, SMEM_DYN>>>(
            s, 1, LC, DD, nullptr, vh, rinv, 0, DD,
            (long long)LQ * LC, (long long)LC * DD, (long long)LQ * DD, 1.0f);
    }
    // G4: out = context @ Woc^T + q @ Woq^T (flat M=32768, 2 segs) -> fp32
    {
        GemmArgs s = { vh, woch, qh, woqh };
        hgemm<0,0><<<dim3(DD / BN, (BB * LQ) / BM, 1), 256, SMEM_DYN>>>(
            s, 2, DD, DD, out, nullptr, nullptr, 0, DD, 0LL, 0LL, 0LL, 1.0f);
    }
}